// round 2
// baseline (speedup 1.0000x reference)
#include <cuda_runtime.h>
#include <math.h>

// ---------------- constants ----------------
#define THREADS1 128
#define NWARPS   4
#define SLOTS    1024          // per-warp candidate-window slots (window <= 32x32)
#define MAXTAB   408           // max distinct assigned cells per (b,level): 40*10 + pad
#define NGT      40
#define EPSF     1e-7f
#define FULLMASK 0xffffffffu
#define NBL      192           // 64 batches * 3 levels

// scratch (device globals; no allocation)
__device__ float g_part[NBL * 4];      // per (b,level): obj_corr, box_sum, foot_sum, npos_count
__device__ float g_obj0part[64 * 6];   // dense z=0 focal partials: 4 chunks lvl0, 1 lvl1, 1 lvl2

struct Stage {
    int   n_pos;
    int   cells[10];
    float best_iou, cxg, cyg, twt, tht, fx, fy;
};

__device__ __forceinline__ float sigf(float x)  { return 1.0f / (1.0f + expf(-x)); }
__device__ __forceinline__ float splus(float x) { return fmaxf(x, 0.0f) + log1pf(expf(-fabsf(x))); }

// decode pred box at cell and IoU vs gt xyxy (assignment-style IoU)
__device__ __forceinline__ float pred_iou(const float* __restrict__ pred, int HW, int cell,
                                          float gxx, float gyy, float s,
                                          float tx1, float ty1, float tx2, float ty2, float tA)
{
    float p1 = pred[HW + cell];
    float p2 = pred[2 * HW + cell];
    float p3 = pred[3 * HW + cell];
    float p4 = pred[4 * HW + cell];
    float pcx = (sigf(p1) + gxx) * s;
    float pcy = (sigf(p2) + gyy) * s;
    float pw  = expf(fminf(fmaxf(p3, -5.0f), 5.0f)) * s;
    float ph  = expf(fminf(fmaxf(p4, -5.0f), 5.0f)) * s;
    float px1 = pcx - pw * 0.5f, py1 = pcy - ph * 0.5f;
    float px2 = pcx + pw * 0.5f, py2 = pcy + ph * 0.5f;
    float iw = fmaxf(fminf(px2, tx2) - fmaxf(px1, tx1), 0.0f);
    float ih = fmaxf(fminf(py2, ty2) - fmaxf(py1, ty1), 0.0f);
    float inter = iw * ih;
    float aa = (px2 - px1) * (py2 - py1);
    return inter / (aa + tA - inter + EPSF);
}

// ---------------- Kernel 1: assignment + sparse losses ----------------
__global__ void __launch_bounds__(THREADS1)
assign_kernel(const float* __restrict__ p0,
              const float* __restrict__ p1,
              const float* __restrict__ p2,
              const float* __restrict__ tgt)
{
    __shared__ float sT[NGT * 7];
    __shared__ float slotCost[NWARPS * SLOTS];
    __shared__ Stage stage[NGT];
    __shared__ int   tabCell[MAXTAB];
    __shared__ float tabObj[MAXTAB], tabTx[MAXTAB], tabTy[MAXTAB];
    __shared__ float tabTw[MAXTAB], tabTh[MAXTAB], tabFx[MAXTAB], tabFy[MAXTAB];
    __shared__ float red[THREADS1];
    __shared__ int   sTabN;

    const int bl    = blockIdx.x;
    const int b     = bl / 3;
    const int level = bl % 3;
    const float* pred = (level == 0) ? p0 : (level == 1) ? p1 : p2;
    const int W  = (level == 0) ? 160 : (level == 1) ? 80 : 40;
    const int H  = W;
    const int HW = H * W;
    const float s = (level == 0) ? 0.00625f : (level == 1) ? 0.0125f : 0.025f;
    pred += (long long)b * 7 * HW;

    const int tid  = threadIdx.x;
    const int lane = tid & 31;
    const int wid  = tid >> 5;

    for (int i = tid; i < NGT * 7; i += THREADS1) sT[i] = tgt[b * NGT * 7 + i];
    __syncthreads();

    const float INF = __int_as_float(0x7f800000);

    // ---- phase A: each warp evaluates GTs (round-robin) ----
    for (int g = wid; g < NGT; g += NWARPS) {
        Stage& st = stage[g];
        const float* t = &sT[g * 7];
        float cls = t[0], cx = t[1], cy = t[2], w = t[3], h = t[4], fx = t[5], fy = t[6];
        float size = fmaxf(w, h) * 1280.0f;
        bool valid = (cls == 0.0f) &&
                     ((level == 0) ? (size < 128.0f)
                      : (level == 1) ? (size >= 48.0f && size < 288.0f)
                                     : (size >= 128.0f));
        if (!valid) { if (lane == 0) st.n_pos = 0; continue; }

        float cxg = cx / s, cyg = cy / s;
        float x1b = (cx - w * 0.5f) / s, x2b = (cx + w * 0.5f) / s;
        float y1b = (cy - h * 0.5f) / s, y2b = (cy + h * 0.5f) / s;
        float tx1 = cx - w * 0.5f, ty1 = cy - h * 0.5f;
        float tx2 = cx + w * 0.5f, ty2 = cy + h * 0.5f;
        float tA  = (tx2 - tx1) * (ty2 - ty1);

        int gx0 = max(0, (int)floorf(fminf(cxg - 2.5f, x1b)));
        int gx1 = min(W - 1, (int)ceilf(fmaxf(cxg + 2.5f, x2b)));
        int gy0 = max(0, (int)floorf(fminf(cyg - 2.5f, y1b)));
        int gy1 = min(H - 1, (int)ceilf(fmaxf(cyg + 2.5f, y2b)));
        int wx = gx1 - gx0 + 1, wy = gy1 - gy0 + 1;
        if (wx > 32) wx = 32;
        if (wy > 32) wy = 32;
        int nwin = (wx > 0 && wy > 0) ? wx * wy : 0;

        float* mc = &slotCost[wid * SLOTS];
        float lis = 0.0f;
        int   lnc = 0;
        for (int si = lane; si < nwin; si += 32) {
            int iy = si / wx, ix = si - iy * wx;
            float gxx = (float)(gx0 + ix), gyy = (float)(gy0 + iy);
            bool ic = (fabsf(gxx - cxg) < 2.5f) && (fabsf(gyy - cyg) < 2.5f);
            bool ib = (gxx >= x1b) && (gxx < x2b) && (gyy >= y1b) && (gyy < y2b);
            float c = INF;
            if (ic || ib) {
                int cell = (gy0 + iy) * W + (gx0 + ix);
                float iou  = pred_iou(pred, HW, cell, gxx, gyy, s, tx1, ty1, tx2, ty2, tA);
                float p0v  = pred[cell];
                float clsc = splus(-p0v);
                c = clsc - 3.0f * logf(iou + EPSF);
                lis += iou;
                lnc += 1;
            }
            mc[si] = c;
        }
        __syncwarp();
        // deterministic warp reduce (butterfly)
        for (int off = 16; off; off >>= 1) {
            lis += __shfl_xor_sync(FULLMASK, lis, off);
            lnc += __shfl_xor_sync(FULLMASK, lnc, off);
        }

        int n_pos;
        float best_iou = 0.0f;
        if (lnc == 0) {
            // fallback: nearest cell (full plane), tie -> smaller index
            float bd = INF; int bc = 0x7fffffff;
            for (int cell = lane; cell < HW; cell += 32) {
                float gxx = (float)(cell % W), gyy = (float)(cell / W);
                float d = (gxx - cxg) * (gxx - cxg) + (gyy - cyg) * (gyy - cyg);
                if (d < bd) { bd = d; bc = cell; }
            }
            for (int off = 16; off; off >>= 1) {
                float od = __shfl_xor_sync(FULLMASK, bd, off);
                int   oc = __shfl_xor_sync(FULLMASK, bc, off);
                if (od < bd || (od == bd && oc < bc)) { bd = od; bc = oc; }
            }
            n_pos = 1;
            float gxx = (float)(bc % W), gyy = (float)(bc / W);
            best_iou = pred_iou(pred, HW, bc, gxx, gyy, s, tx1, ty1, tx2, ty2, tA);
            if (lane == 0) st.cells[0] = bc;
        } else {
            int hi = min(10, lnc);
            int fl = (int)floorf(lis);
            n_pos = min(hi, max(1, fl));
            for (int k = 0; k < n_pos; k++) {
                float bcst = INF; int bs = 0x7fffffff;
                for (int si = lane; si < nwin; si += 32) {
                    float cc = mc[si];
                    if (cc < bcst) { bcst = cc; bs = si; }
                }
                for (int off = 16; off; off >>= 1) {
                    float oc = __shfl_xor_sync(FULLMASK, bcst, off);
                    int   os = __shfl_xor_sync(FULLMASK, bs, off);
                    if (oc < bcst || (oc == bcst && os < bs)) { bcst = oc; bs = os; }
                }
                int iy = bs / wx, ix = bs - iy * wx;
                int cell = (gy0 + iy) * W + (gx0 + ix);
                if (k == 0) {
                    float gxx = (float)(gx0 + ix), gyy = (float)(gy0 + iy);
                    best_iou = pred_iou(pred, HW, cell, gxx, gyy, s, tx1, ty1, tx2, ty2, tA);
                }
                if (lane == 0) { st.cells[k] = cell; mc[bs] = INF; }
                __syncwarp();
            }
        }
        if (lane == 0) {
            st.n_pos    = n_pos;
            st.best_iou = best_iou;
            st.cxg = cxg; st.cyg = cyg;
            st.twt = logf(w / s + EPSF);
            st.tht = logf(h / s + EPSF);
            st.fx = fx; st.fy = fy;
        }
    }
    __syncthreads();

    // ---- phase B: serial apply in GT order (warp 0) into compact table ----
    if (wid == 0) {
        int tabN = 0;
        for (int g = 0; g < NGT; g++) {
            int np = stage[g].n_pos;
            if (np == 0) continue;
            float biou = stage[g].best_iou;
            float cxg = stage[g].cxg, cyg = stage[g].cyg;
            float twt = stage[g].twt, tht = stage[g].tht;
            float sfx = stage[g].fx,  sfy = stage[g].fy;
            for (int k = 0; k < np; k++) {
                int c = stage[g].cells[k];
                int entry = -1;
                for (int base = 0; base < tabN; base += 32) {
                    int i = base + lane;
                    bool hit = (i < tabN) && (tabCell[i] == c);
                    unsigned m = __ballot_sync(FULLMASK, hit);
                    if (m) { entry = base + __ffs(m) - 1; break; }
                }
                if (entry < 0) {
                    entry = tabN++;
                    if (lane == 0) { tabCell[entry] = c; tabObj[entry] = 0.0f; }
                }
                __syncwarp();
                if (lane == 0) {
                    tabObj[entry] = fmaxf(tabObj[entry], biou);
                    tabTx[entry]  = cxg - (float)(c % W);
                    tabTy[entry]  = cyg - (float)(c / W);
                    tabTw[entry]  = twt; tabTh[entry] = tht;
                    tabFx[entry]  = sfx; tabFy[entry] = sfy;
                }
                __syncwarp();
            }
        }
        if (lane == 0) sTabN = tabN;
    }
    __syncthreads();

    // ---- phase C: sparse losses at table cells ----
    int tabN = sTabN;
    float corr = 0.0f, boxs = 0.0f, foots = 0.0f;
    for (int i = tid; i < tabN; i += THREADS1) {
        int c = tabCell[i];
        float gxx = (float)(c % W), gyy = (float)(c / W);
        float x = pred[c];
        float z = tabObj[i];
        float prob = sigf(x);
        float l1e  = log1pf(expf(-fabsf(x)));
        float ce   = fmaxf(x, 0.0f) - x * z + l1e;
        float ce0  = fmaxf(x, 0.0f) + l1e;
        float pt   = prob * z + (1.0f - prob) * (1.0f - z);
        float at   = 0.25f * z + 0.75f * (1.0f - z);
        float om   = 1.0f - pt;
        float term  = at * om * om * ce;
        float term0 = 0.75f * prob * prob * ce0;
        corr += term - term0;

        // box (CIoU)
        float p1v = pred[HW + c], p2v = pred[2 * HW + c];
        float p3v = pred[3 * HW + c], p4v = pred[4 * HW + c];
        float pcx = (sigf(p1v) + gxx) * s;
        float pcy = (sigf(p2v) + gyy) * s;
        float pw  = expf(fminf(fmaxf(p3v, -5.0f), 5.0f)) * s;
        float ph  = expf(fminf(fmaxf(p4v, -5.0f), 5.0f)) * s;
        float tcx = (tabTx[i] + gxx) * s;
        float tcy = (tabTy[i] + gyy) * s;
        float tw  = expf(tabTw[i]) * s;
        float th  = expf(tabTh[i]) * s;
        float px1 = pcx - pw * 0.5f, py1 = pcy - ph * 0.5f;
        float px2 = pcx + pw * 0.5f, py2 = pcy + ph * 0.5f;
        float qx1 = tcx - tw * 0.5f, qy1 = tcy - th * 0.5f;
        float qx2 = tcx + tw * 0.5f, qy2 = tcy + th * 0.5f;
        float iw = fmaxf(fminf(px2, qx2) - fmaxf(px1, qx1), 0.0f);
        float ih = fmaxf(fminf(py2, qy2) - fmaxf(py1, qy1), 0.0f);
        float inter = iw * ih;
        float uni = pw * ph + tw * th - inter + EPSF;
        float iou = inter / uni;
        float rho2 = (pcx - tcx) * (pcx - tcx) + (pcy - tcy) * (pcy - tcy);
        float cw = fmaxf(px2, qx2) - fminf(px1, qx1);
        float chh = fmaxf(py2, qy2) - fminf(py1, qy1);
        float c2 = cw * cw + chh * chh + EPSF;
        float dat = atanf(tw / (th + EPSF)) - atanf(pw / (ph + EPSF));
        float v = 0.4052847345693511f * dat * dat;
        float alpha = v / (1.0f - iou + v + EPSF);
        float ciou = iou - rho2 / c2 - alpha * v;
        boxs += 1.0f - ciou;

        // foot (smooth L1 on sigmoid(p5:7))
        float p5v = pred[5 * HW + c], p6v = pred[6 * HW + c];
        float d1 = fabsf(sigf(p5v) - tabFx[i]);
        float d2 = fabsf(sigf(p6v) - tabFy[i]);
        float s1 = (d1 < 1.0f) ? 0.5f * d1 * d1 : d1 - 0.5f;
        float s2 = (d2 < 1.0f) ? 0.5f * d2 * d2 : d2 - 0.5f;
        foots += s1 + s2;
    }

    // deterministic block reductions
    red[tid] = corr; __syncthreads();
    for (int off = THREADS1 / 2; off; off >>= 1) { if (tid < off) red[tid] += red[tid + off]; __syncthreads(); }
    if (tid == 0) g_part[bl * 4 + 0] = red[0];
    __syncthreads();
    red[tid] = boxs; __syncthreads();
    for (int off = THREADS1 / 2; off; off >>= 1) { if (tid < off) red[tid] += red[tid + off]; __syncthreads(); }
    if (tid == 0) g_part[bl * 4 + 1] = red[0];
    __syncthreads();
    red[tid] = foots; __syncthreads();
    for (int off = THREADS1 / 2; off; off >>= 1) { if (tid < off) red[tid] += red[tid + off]; __syncthreads(); }
    if (tid == 0) {
        g_part[bl * 4 + 2] = red[0];
        g_part[bl * 4 + 3] = (float)tabN;   // sum(pm)
    }
}

// ---------------- Kernel 2: dense z=0 focal partial sums ----------------
__global__ void __launch_bounds__(256)
obj0_kernel(const float* __restrict__ p0,
            const float* __restrict__ p1,
            const float* __restrict__ p2)
{
    __shared__ float red[256];
    int blk = blockIdx.x;
    int b = blk / 6, c6 = blk % 6;
    const float* base;
    int off, cnt;
    if (c6 < 4)       { base = p0 + (long long)b * 7 * 25600; off = c6 * 6400; cnt = 6400; }
    else if (c6 == 4) { base = p1 + (long long)b * 7 * 6400;  off = 0;         cnt = 6400; }
    else              { base = p2 + (long long)b * 7 * 1600;  off = 0;         cnt = 1600; }

    float sum = 0.0f;
    for (int i = threadIdx.x; i < cnt; i += 256) {
        float x = base[off + i];
        float prob = 1.0f / (1.0f + expf(-x));
        float ce0  = fmaxf(x, 0.0f) + log1pf(expf(-fabsf(x)));
        sum += 0.75f * prob * prob * ce0;
    }
    red[threadIdx.x] = sum; __syncthreads();
    for (int o = 128; o; o >>= 1) { if (threadIdx.x < o) red[threadIdx.x] += red[threadIdx.x + o]; __syncthreads(); }
    if (threadIdx.x == 0) g_obj0part[blk] = red[0];
}

// ---------------- Kernel 3: deterministic final combine ----------------
__global__ void __launch_bounds__(256)
final_kernel(float* __restrict__ out)
{
    __shared__ float red[256];
    int t = threadIdx.x;
    float v = 0.0f;
    if (t < NBL) {
        int b = t / 3, l = t % 3;
        float HWf = (l == 0) ? 25600.0f : (l == 1) ? 6400.0f : 1600.0f;
        float obj0;
        if (l == 0)      obj0 = g_obj0part[b * 6 + 0] + g_obj0part[b * 6 + 1] +
                                g_obj0part[b * 6 + 2] + g_obj0part[b * 6 + 3];
        else if (l == 1) obj0 = g_obj0part[b * 6 + 4];
        else             obj0 = g_obj0part[b * 6 + 5];
        float corr  = g_part[t * 4 + 0];
        float boxs  = g_part[t * 4 + 1];
        float foots = g_part[t * 4 + 2];
        float npos  = fmaxf(g_part[t * 4 + 3], 1.0f);
        v = (obj0 + corr) / HWf + 5.0f * boxs / npos + foots / npos;
    }
    red[t] = v; __syncthreads();
    for (int o = 128; o; o >>= 1) { if (t < o) red[t] += red[t + o]; __syncthreads(); }
    if (t == 0) out[0] = red[0] / 64.0f;
}

// ---------------- launch ----------------
extern "C" void kernel_launch(void* const* d_in, const int* in_sizes, int n_in,
                              void* d_out, int out_size)
{
    const float* p0  = (const float*)d_in[0];
    const float* p1  = (const float*)d_in[1];
    const float* p2  = (const float*)d_in[2];
    const float* tgt = (const float*)d_in[3];

    assign_kernel<<<NBL, THREADS1>>>(p0, p1, p2, tgt);
    obj0_kernel<<<64 * 6, 256>>>(p0, p1, p2);
    final_kernel<<<1, 256>>>((float*)d_out);
}

// round 4
// speedup vs baseline: 1.4949x; 1.4949x over previous
#include <cuda_runtime.h>
#include <math.h>

// ---------------- constants ----------------
#define SLOTS    1024          // per-warp candidate-window slots (window <= 32x32)
#define NGT      40
#define EPSF     1e-7f
#define FULLMASK 0xffffffffu
#define NBL      192           // 64 batches * 3 levels
#define WPB      8             // warps per block in stage kernel
#define MAXENT   400           // max entries per (b,level) = NGT*10

struct Stage {
    int   n_pos;
    int   cells[10];
    float biou, cxg, cyg, twt, tht, fx, fy;
};

__device__ Stage g_stage[NBL * NGT];
__device__ float g_part[NBL * 4];   // per (b,level): obj_total, box_sum, foot_sum, npos

__device__ __forceinline__ float sigf(float x)  { return 1.0f / (1.0f + expf(-x)); }
__device__ __forceinline__ float splus(float x) { return fmaxf(x, 0.0f) + log1pf(expf(-fabsf(x))); }

// decode pred box at cell and IoU vs gt xyxy (assignment-style IoU)
__device__ __forceinline__ float pred_iou(const float* __restrict__ pred, int HW, int cell,
                                          float gxx, float gyy, float s,
                                          float tx1, float ty1, float tx2, float ty2, float tA)
{
    float p1 = pred[HW + cell];
    float p2 = pred[2 * HW + cell];
    float p3 = pred[3 * HW + cell];
    float p4 = pred[4 * HW + cell];
    float pcx = (sigf(p1) + gxx) * s;
    float pcy = (sigf(p2) + gyy) * s;
    float pw  = expf(fminf(fmaxf(p3, -5.0f), 5.0f)) * s;
    float ph  = expf(fminf(fmaxf(p4, -5.0f), 5.0f)) * s;
    float px1 = pcx - pw * 0.5f, py1 = pcy - ph * 0.5f;
    float px2 = pcx + pw * 0.5f, py2 = pcy + ph * 0.5f;
    float iw = fmaxf(fminf(px2, tx2) - fmaxf(px1, tx1), 0.0f);
    float ih = fmaxf(fminf(py2, ty2) - fmaxf(py1, ty1), 0.0f);
    float inter = iw * ih;
    float aa = (px2 - px1) * (py2 - py1);
    return inter / (aa + tA - inter + EPSF);
}

// ---------------- Kernel 1: per-GT candidate selection (1 warp per (b,level,gt)) ----------------
__global__ void __launch_bounds__(WPB * 32)
stage_kernel(const float* __restrict__ p0,
             const float* __restrict__ p1,
             const float* __restrict__ p2,
             const float* __restrict__ tgt)
{
    __shared__ float slotCost[WPB * SLOTS];

    const int lane = threadIdx.x & 31;
    const int wloc = threadIdx.x >> 5;
    const int gw   = blockIdx.x * WPB + wloc;
    if (gw >= NBL * NGT) return;

    const int bl    = gw / NGT;
    const int g     = gw - bl * NGT;
    const int b     = bl / 3;
    const int level = bl % 3;

    Stage& st = g_stage[gw];

    const float* t = &tgt[b * NGT * 7 + g * 7];
    float cls = t[0], cx = t[1], cy = t[2], w = t[3], h = t[4], fx = t[5], fy = t[6];
    float size = fmaxf(w, h) * 1280.0f;
    bool valid = (cls == 0.0f) &&
                 ((level == 0) ? (size < 128.0f)
                  : (level == 1) ? (size >= 48.0f && size < 288.0f)
                                 : (size >= 128.0f));
    if (!valid) { if (lane == 0) st.n_pos = 0; return; }

    const float* pred = (level == 0) ? p0 : (level == 1) ? p1 : p2;
    const int W  = (level == 0) ? 160 : (level == 1) ? 80 : 40;
    const int H  = W;
    const int HW = H * W;
    const float s = (level == 0) ? 0.00625f : (level == 1) ? 0.0125f : 0.025f;
    pred += (long long)b * 7 * HW;

    const float INF = __int_as_float(0x7f800000);

    float cxg = cx / s, cyg = cy / s;
    float x1b = (cx - w * 0.5f) / s, x2b = (cx + w * 0.5f) / s;
    float y1b = (cy - h * 0.5f) / s, y2b = (cy + h * 0.5f) / s;
    float tx1 = cx - w * 0.5f, ty1 = cy - h * 0.5f;
    float tx2 = cx + w * 0.5f, ty2 = cy + h * 0.5f;
    float tA  = (tx2 - tx1) * (ty2 - ty1);

    int gx0 = max(0, (int)floorf(fminf(cxg - 2.5f, x1b)));
    int gx1 = min(W - 1, (int)ceilf(fmaxf(cxg + 2.5f, x2b)));
    int gy0 = max(0, (int)floorf(fminf(cyg - 2.5f, y1b)));
    int gy1 = min(H - 1, (int)ceilf(fmaxf(cyg + 2.5f, y2b)));
    int wx = gx1 - gx0 + 1, wy = gy1 - gy0 + 1;
    if (wx > 32) wx = 32;
    if (wy > 32) wy = 32;
    int nwin = (wx > 0 && wy > 0) ? wx * wy : 0;

    float* mc = &slotCost[wloc * SLOTS];
    float lis = 0.0f;
    int   lnc = 0;
    for (int si = lane; si < nwin; si += 32) {
        int iy = si / wx, ix = si - iy * wx;
        float gxx = (float)(gx0 + ix), gyy = (float)(gy0 + iy);
        bool ic = (fabsf(gxx - cxg) < 2.5f) && (fabsf(gyy - cyg) < 2.5f);
        bool ib = (gxx >= x1b) && (gxx < x2b) && (gyy >= y1b) && (gyy < y2b);
        float c = INF;
        if (ic || ib) {
            int cell = (gy0 + iy) * W + (gx0 + ix);
            float iou  = pred_iou(pred, HW, cell, gxx, gyy, s, tx1, ty1, tx2, ty2, tA);
            float p0v  = pred[cell];
            float clsc = splus(-p0v);
            c = clsc - 3.0f * logf(iou + EPSF);
            lis += iou;
            lnc += 1;
        }
        mc[si] = c;
    }
    __syncwarp();
    for (int off = 16; off; off >>= 1) {
        lis += __shfl_xor_sync(FULLMASK, lis, off);
        lnc += __shfl_xor_sync(FULLMASK, lnc, off);
    }

    int n_pos;
    float best_iou = 0.0f;
    if (lnc == 0) {
        // fallback: nearest cell (full plane), tie -> smaller index
        float bd = INF; int bc = 0x7fffffff;
        for (int cell = lane; cell < HW; cell += 32) {
            float gxx = (float)(cell % W), gyy = (float)(cell / W);
            float d = (gxx - cxg) * (gxx - cxg) + (gyy - cyg) * (gyy - cyg);
            if (d < bd) { bd = d; bc = cell; }
        }
        for (int off = 16; off; off >>= 1) {
            float od = __shfl_xor_sync(FULLMASK, bd, off);
            int   oc = __shfl_xor_sync(FULLMASK, bc, off);
            if (od < bd || (od == bd && oc < bc)) { bd = od; bc = oc; }
        }
        n_pos = 1;
        float gxx = (float)(bc % W), gyy = (float)(bc / W);
        best_iou = pred_iou(pred, HW, bc, gxx, gyy, s, tx1, ty1, tx2, ty2, tA);
        if (lane == 0) st.cells[0] = bc;
    } else {
        int hi = min(10, lnc);
        int fl = (int)floorf(lis);
        n_pos = min(hi, max(1, fl));
        for (int k = 0; k < n_pos; k++) {
            float bcst = INF; int bs = 0x7fffffff;
            for (int si = lane; si < nwin; si += 32) {
                float cc = mc[si];
                if (cc < bcst) { bcst = cc; bs = si; }
            }
            for (int off = 16; off; off >>= 1) {
                float oc = __shfl_xor_sync(FULLMASK, bcst, off);
                int   os = __shfl_xor_sync(FULLMASK, bs, off);
                if (oc < bcst || (oc == bcst && os < bs)) { bcst = oc; bs = os; }
            }
            int iy = bs / wx, ix = bs - iy * wx;
            int cell = (gy0 + iy) * W + (gx0 + ix);
            if (k == 0) {
                float gxx = (float)(gx0 + ix), gyy = (float)(gy0 + iy);
                best_iou = pred_iou(pred, HW, cell, gxx, gyy, s, tx1, ty1, tx2, ty2, tA);
            }
            if (lane == 0) { st.cells[k] = cell; mc[bs] = INF; }
            __syncwarp();
        }
    }
    if (lane == 0) {
        st.n_pos = n_pos;
        st.biou  = best_iou;
        st.cxg = cxg; st.cyg = cyg;
        st.twt = logf(w / s + EPSF);
        st.tht = logf(h / s + EPSF);
        st.fx = fx; st.fy = fy;
    }
}

// ---------------- Kernel 2: deterministic parallel apply + losses + dense focal ----------------
__global__ void __launch_bounds__(128)
apply_kernel(const float* __restrict__ p0,
             const float* __restrict__ p1,
             const float* __restrict__ p2)
{
    __shared__ int   entCell[MAXENT];
    __shared__ int   entG[MAXENT];
    __shared__ float sBiou[NGT], sCxg[NGT], sCyg[NGT], sTwt[NGT], sTht[NGT], sFx[NGT], sFy[NGT];
    __shared__ int   sNp[NGT], sOff[NGT];
    __shared__ int   sM;
    __shared__ float red[128];

    const int bl    = blockIdx.x;
    const int b     = bl / 3;
    const int level = bl % 3;
    const float* pred = (level == 0) ? p0 : (level == 1) ? p1 : p2;
    const int W  = (level == 0) ? 160 : (level == 1) ? 80 : 40;
    const int HW = W * W;
    const float s = (level == 0) ? 0.00625f : (level == 1) ? 0.0125f : 0.025f;
    pred += (long long)b * 7 * HW;

    const int tid = threadIdx.x;

    // load per-GT stage scalars
    if (tid < NGT) {
        const Stage& st = g_stage[bl * NGT + tid];
        int np = st.n_pos;
        sNp[tid]   = np;
        sBiou[tid] = st.biou;
        sCxg[tid]  = st.cxg;  sCyg[tid] = st.cyg;
        sTwt[tid]  = st.twt;  sTht[tid] = st.tht;
        sFx[tid]   = st.fx;   sFy[tid]  = st.fy;
    }
    __syncthreads();
    if (tid < NGT) {
        int off = 0;
        #pragma unroll
        for (int g2 = 0; g2 < NGT; g2++) { if (g2 < tid) off += sNp[g2]; }
        sOff[tid] = off;
        if (tid == NGT - 1) sM = off + sNp[tid];
    }
    __syncthreads();
    // fill compact entry list in GT order
    if (tid < NGT) {
        const Stage& st = g_stage[bl * NGT + tid];
        int off = sOff[tid];
        int np  = sNp[tid];
        for (int k = 0; k < np; k++) { entCell[off + k] = st.cells[k]; entG[off + k] = tid; }
    }
    __syncthreads();
    const int M = sM;

    float corr = 0.0f, boxs = 0.0f, foots = 0.0f;
    int   nown = 0;

    // ---- resolve + sparse losses ----
    for (int e = tid; e < M; e += 128) {
        int c  = entCell[e];
        int ge = entG[e];
        float z = sBiou[ge];
        bool owner = true;
        for (int e2 = 0; e2 < M; e2++) {
            if (entCell[e2] == c && e2 != e) {
                int g2 = entG[e2];
                z = fmaxf(z, sBiou[g2]);
                if (g2 > ge) owner = false;
            }
        }
        if (!owner) continue;
        nown++;

        float gxx = (float)(c % W), gyy = (float)(c / W);

        // focal correction: full term with z minus z=0 term (added densely below)
        float x = pred[c];
        float prob = sigf(x);
        float l1e  = log1pf(expf(-fabsf(x)));
        float ce   = fmaxf(x, 0.0f) - x * z + l1e;
        float ce0  = fmaxf(x, 0.0f) + l1e;
        float pt   = prob * z + (1.0f - prob) * (1.0f - z);
        float at   = 0.25f * z + 0.75f * (1.0f - z);
        float om   = 1.0f - pt;
        corr += at * om * om * ce - 0.75f * prob * prob * ce0;

        // box (CIoU) with last-writer (this entry's) targets
        float p1v = pred[HW + c], p2v = pred[2 * HW + c];
        float p3v = pred[3 * HW + c], p4v = pred[4 * HW + c];
        float pcx = (sigf(p1v) + gxx) * s;
        float pcy = (sigf(p2v) + gyy) * s;
        float pw  = expf(fminf(fmaxf(p3v, -5.0f), 5.0f)) * s;
        float ph  = expf(fminf(fmaxf(p4v, -5.0f), 5.0f)) * s;
        float tcx = sCxg[ge] * s;                 // (tx + gx)*s == cxg*s
        float tcy = sCyg[ge] * s;
        float tw  = expf(sTwt[ge]) * s;
        float th  = expf(sTht[ge]) * s;
        float px1 = pcx - pw * 0.5f, py1 = pcy - ph * 0.5f;
        float px2 = pcx + pw * 0.5f, py2 = pcy + ph * 0.5f;
        float qx1 = tcx - tw * 0.5f, qy1 = tcy - th * 0.5f;
        float qx2 = tcx + tw * 0.5f, qy2 = tcy + th * 0.5f;
        float iw = fmaxf(fminf(px2, qx2) - fmaxf(px1, qx1), 0.0f);
        float ih = fmaxf(fminf(py2, qy2) - fmaxf(py1, qy1), 0.0f);
        float inter = iw * ih;
        float uni = pw * ph + tw * th - inter + EPSF;
        float iou = inter / uni;
        float rho2 = (pcx - tcx) * (pcx - tcx) + (pcy - tcy) * (pcy - tcy);
        float cw  = fmaxf(px2, qx2) - fminf(px1, qx1);
        float chh = fmaxf(py2, qy2) - fminf(py1, qy1);
        float c2  = cw * cw + chh * chh + EPSF;
        float dat = atanf(tw / (th + EPSF)) - atanf(pw / (ph + EPSF));
        float v = 0.4052847345693511f * dat * dat;
        float alpha = v / (1.0f - iou + v + EPSF);
        float ciou = iou - rho2 / c2 - alpha * v;
        boxs += 1.0f - ciou;

        // foot (smooth L1)
        float p5v = pred[5 * HW + c], p6v = pred[6 * HW + c];
        float d1 = fabsf(sigf(p5v) - sFx[ge]);
        float d2 = fabsf(sigf(p6v) - sFy[ge]);
        float s1 = (d1 < 1.0f) ? 0.5f * d1 * d1 : d1 - 0.5f;
        float s2 = (d2 < 1.0f) ? 0.5f * d2 * d2 : d2 - 0.5f;
        foots += s1 + s2;
    }

    // ---- dense z=0 focal over channel 0 (vectorized) ----
    float osum = 0.0f;
    const float4* v4 = (const float4*)pred;
    for (int i = tid; i < HW / 4; i += 128) {
        float4 xv = v4[i];
        #pragma unroll
        for (int j = 0; j < 4; j++) {
            float x = (j == 0) ? xv.x : (j == 1) ? xv.y : (j == 2) ? xv.z : xv.w;
            float prob = 1.0f / (1.0f + expf(-x));
            float ce0  = fmaxf(x, 0.0f) + log1pf(expf(-fabsf(x)));
            osum += 0.75f * prob * prob * ce0;
        }
    }
    corr += osum;   // obj_total partial = dense z=0 sum + sparse correction

    // ---- deterministic block reductions ----
    red[tid] = corr; __syncthreads();
    for (int off = 64; off; off >>= 1) { if (tid < off) red[tid] += red[tid + off]; __syncthreads(); }
    if (tid == 0) g_part[bl * 4 + 0] = red[0];
    __syncthreads();
    red[tid] = boxs; __syncthreads();
    for (int off = 64; off; off >>= 1) { if (tid < off) red[tid] += red[tid + off]; __syncthreads(); }
    if (tid == 0) g_part[bl * 4 + 1] = red[0];
    __syncthreads();
    red[tid] = foots; __syncthreads();
    for (int off = 64; off; off >>= 1) { if (tid < off) red[tid] += red[tid + off]; __syncthreads(); }
    if (tid == 0) g_part[bl * 4 + 2] = red[0];
    __syncthreads();
    red[tid] = (float)nown; __syncthreads();
    for (int off = 64; off; off >>= 1) { if (tid < off) red[tid] += red[tid + off]; __syncthreads(); }
    if (tid == 0) g_part[bl * 4 + 3] = red[0];
}

// ---------------- Kernel 3: deterministic final combine ----------------
__global__ void __launch_bounds__(256)
final_kernel(float* __restrict__ out)
{
    __shared__ float red[256];
    int t = threadIdx.x;
    float v = 0.0f;
    if (t < NBL) {
        int l = t % 3;
        float HWf = (l == 0) ? 25600.0f : (l == 1) ? 6400.0f : 1600.0f;
        float objt  = g_part[t * 4 + 0];
        float boxs  = g_part[t * 4 + 1];
        float foots = g_part[t * 4 + 2];
        float npos  = fmaxf(g_part[t * 4 + 3], 1.0f);
        v = objt / HWf + 5.0f * boxs / npos + foots / npos;
    }
    red[t] = v; __syncthreads();
    for (int o = 128; o; o >>= 1) { if (t < o) red[t] += red[t + o]; __syncthreads(); }
    if (t == 0) out[0] = red[0] / 64.0f;
}

// ---------------- launch ----------------
extern "C" void kernel_launch(void* const* d_in, const int* in_sizes, int n_in,
                              void* d_out, int out_size)
{
    const float* p0  = (const float*)d_in[0];
    const float* p1  = (const float*)d_in[1];
    const float* p2  = (const float*)d_in[2];
    const float* tgt = (const float*)d_in[3];

    stage_kernel<<<(NBL * NGT + WPB - 1) / WPB, WPB * 32>>>(p0, p1, p2, tgt);
    apply_kernel<<<NBL, 128>>>(p0, p1, p2);
    final_kernel<<<1, 256>>>((float*)d_out);
}

// round 6
// speedup vs baseline: 2.5717x; 1.7203x over previous
#include <cuda_runtime.h>
#include <math.h>

// ---------------- constants ----------------
#define MAXW     24            // max candidate-window side (scale masks bound it to <=21)
#define SLOTS    (MAXW*MAXW)   // 576
#define NGT      40
#define EPSF     1e-7f
#define FULLMASK 0xffffffffu
#define NBL      192           // 64 batches * 3 levels
#define WPB      8             // warps per block in stage kernel
#define MAXENT   400           // max entries per (b,level) = NGT*10

struct Stage {
    int   n_pos;
    int   cells[10];
    float biou, cxg, cyg, twt, tht, fx, fy;
};

__device__ Stage g_stage[NBL * NGT];
__device__ float g_focal[NBL * NGT];  // per-warp dense z=0 focal partial
__device__ float g_part[NBL * 4];     // per (b,level): obj_total, box_sum, foot_sum, npos

__device__ __forceinline__ float sigf(float x)  { return 1.0f / (1.0f + expf(-x)); }
__device__ __forceinline__ float splus(float x) { return fmaxf(x, 0.0f) + log1pf(expf(-fabsf(x))); }

// fast z=0 focal term: 0.75 * sigmoid(x)^2 * softplus(x)   (3 MUFU ops)
__device__ __forceinline__ float focal0(float x) {
    float t   = __expf(-fabsf(x));
    float inv = __fdividef(1.0f, 1.0f + t);
    float prob = (x >= 0.0f) ? inv : t * inv;
    float ce0  = fmaxf(x, 0.0f) + __logf(1.0f + t);
    return 0.75f * prob * prob * ce0;
}

// decode pred box at cell and IoU vs gt xyxy (assignment-style IoU) -- precise math
__device__ __forceinline__ float pred_iou(const float* __restrict__ pred, int HW, int cell,
                                          float gxx, float gyy, float s,
                                          float tx1, float ty1, float tx2, float ty2, float tA)
{
    float p1 = pred[HW + cell];
    float p2 = pred[2 * HW + cell];
    float p3 = pred[3 * HW + cell];
    float p4 = pred[4 * HW + cell];
    float pcx = (sigf(p1) + gxx) * s;
    float pcy = (sigf(p2) + gyy) * s;
    float pw  = expf(fminf(fmaxf(p3, -5.0f), 5.0f)) * s;
    float ph  = expf(fminf(fmaxf(p4, -5.0f), 5.0f)) * s;
    float px1 = pcx - pw * 0.5f, py1 = pcy - ph * 0.5f;
    float px2 = pcx + pw * 0.5f, py2 = pcy + ph * 0.5f;
    float iw = fmaxf(fminf(px2, tx2) - fmaxf(px1, tx1), 0.0f);
    float ih = fmaxf(fminf(py2, ty2) - fmaxf(py1, ty1), 0.0f);
    float inter = iw * ih;
    float aa = (px2 - px1) * (py2 - py1);
    return inter / (aa + tA - inter + EPSF);
}

// ---------------- Kernel 1: per-GT selection + fused dense focal slice ----------------
__global__ void __launch_bounds__(WPB * 32)
stage_kernel(const float* __restrict__ p0,
             const float* __restrict__ p1,
             const float* __restrict__ p2,
             const float* __restrict__ tgt)
{
    __shared__ float slotCost[WPB * SLOTS];

    const int lane = threadIdx.x & 31;
    const int wloc = threadIdx.x >> 5;
    const int gw   = blockIdx.x * WPB + wloc;
    if (gw >= NBL * NGT) return;

    const int bl    = gw / NGT;
    const int g     = gw - bl * NGT;
    const int b     = bl / 3;
    const int level = bl % 3;

    const float* predB = (level == 0) ? p0 : (level == 1) ? p1 : p2;
    const int W  = (level == 0) ? 160 : (level == 1) ? 80 : 40;
    const int HW = W * W;
    const float s = (level == 0) ? 0.00625f : (level == 1) ? 0.0125f : 0.025f;
    const float* pred = predB + (long long)b * 7 * HW;

    Stage& st = g_stage[gw];

    const float* t = &tgt[b * NGT * 7 + g * 7];
    float cls = t[0], cx = t[1], cy = t[2], w = t[3], h = t[4], fx = t[5], fy = t[6];
    float size = fmaxf(w, h) * 1280.0f;
    bool valid = (cls == 0.0f) &&
                 ((level == 0) ? (size < 128.0f)
                  : (level == 1) ? (size >= 48.0f && size < 288.0f)
                                 : (size >= 128.0f));

    const float INF = __int_as_float(0x7f800000);

    if (!valid) {
        if (lane == 0) st.n_pos = 0;
    } else {
        float cxg = cx / s, cyg = cy / s;
        float x1b = (cx - w * 0.5f) / s, x2b = (cx + w * 0.5f) / s;
        float y1b = (cy - h * 0.5f) / s, y2b = (cy + h * 0.5f) / s;
        float tx1 = cx - w * 0.5f, ty1 = cy - h * 0.5f;
        float tx2 = cx + w * 0.5f, ty2 = cy + h * 0.5f;
        float tA  = (tx2 - tx1) * (ty2 - ty1);

        int gx0 = max(0, (int)floorf(fminf(cxg - 2.5f, x1b)));
        int gx1 = min(W - 1, (int)ceilf(fmaxf(cxg + 2.5f, x2b)));
        int gy0 = max(0, (int)floorf(fminf(cyg - 2.5f, y1b)));
        int gy1 = min(W - 1, (int)ceilf(fmaxf(cyg + 2.5f, y2b)));
        int wx = gx1 - gx0 + 1, wy = gy1 - gy0 + 1;
        if (wx > MAXW) wx = MAXW;
        if (wy > MAXW) wy = MAXW;
        int nwin = (wx > 0 && wy > 0) ? wx * wy : 0;

        float* mc = &slotCost[wloc * SLOTS];
        float lis = 0.0f;
        int   lnc = 0;
        for (int si = lane; si < nwin; si += 32) {
            int iy = si / wx, ix = si - iy * wx;
            float gxx = (float)(gx0 + ix), gyy = (float)(gy0 + iy);
            bool ic = (fabsf(gxx - cxg) < 2.5f) && (fabsf(gyy - cyg) < 2.5f);
            bool ib = (gxx >= x1b) && (gxx < x2b) && (gyy >= y1b) && (gyy < y2b);
            float c = INF;
            if (ic || ib) {
                int cell = (gy0 + iy) * W + (gx0 + ix);
                float iou  = pred_iou(pred, HW, cell, gxx, gyy, s, tx1, ty1, tx2, ty2, tA);
                float p0v  = pred[cell];
                float clsc = splus(-p0v);
                c = clsc - 3.0f * logf(iou + EPSF);
                lis += iou;
                lnc += 1;
            }
            mc[si] = c;
        }
        __syncwarp();
        for (int off = 16; off; off >>= 1) {
            lis += __shfl_xor_sync(FULLMASK, lis, off);
            lnc += __shfl_xor_sync(FULLMASK, lnc, off);
        }

        int n_pos;
        float best_iou = 0.0f;
        if (lnc == 0) {
            float bd = INF; int bc = 0x7fffffff;
            for (int cell = lane; cell < HW; cell += 32) {
                float gxx = (float)(cell % W), gyy = (float)(cell / W);
                float d = (gxx - cxg) * (gxx - cxg) + (gyy - cyg) * (gyy - cyg);
                if (d < bd) { bd = d; bc = cell; }
            }
            for (int off = 16; off; off >>= 1) {
                float od = __shfl_xor_sync(FULLMASK, bd, off);
                int   oc = __shfl_xor_sync(FULLMASK, bc, off);
                if (od < bd || (od == bd && oc < bc)) { bd = od; bc = oc; }
            }
            n_pos = 1;
            float gxx = (float)(bc % W), gyy = (float)(bc / W);
            best_iou = pred_iou(pred, HW, bc, gxx, gyy, s, tx1, ty1, tx2, ty2, tA);
            if (lane == 0) st.cells[0] = bc;
        } else {
            int hi = min(10, lnc);
            int fl = (int)floorf(lis);
            n_pos = min(hi, max(1, fl));
            for (int k = 0; k < n_pos; k++) {
                float bcst = INF; int bs = 0x7fffffff;
                for (int si = lane; si < nwin; si += 32) {
                    float cc = mc[si];
                    if (cc < bcst) { bcst = cc; bs = si; }
                }
                for (int off = 16; off; off >>= 1) {
                    float oc = __shfl_xor_sync(FULLMASK, bcst, off);
                    int   os = __shfl_xor_sync(FULLMASK, bs, off);
                    if (oc < bcst || (oc == bcst && os < bs)) { bcst = oc; bs = os; }
                }
                int iy = bs / wx, ix = bs - iy * wx;
                int cell = (gy0 + iy) * W + (gx0 + ix);
                if (k == 0) {
                    float gxx = (float)(gx0 + ix), gyy = (float)(gy0 + iy);
                    best_iou = pred_iou(pred, HW, cell, gxx, gyy, s, tx1, ty1, tx2, ty2, tA);
                }
                if (lane == 0) { st.cells[k] = cell; mc[bs] = INF; }
                __syncwarp();
            }
        }
        if (lane == 0) {
            st.n_pos = n_pos;
            st.biou  = best_iou;
            st.cxg = cxg; st.cyg = cyg;
            st.twt = logf(w / s + EPSF);
            st.tht = logf(h / s + EPSF);
            st.fx = fx; st.fy = fy;
        }
    }

    // ---- fused dense z=0 focal: warp g handles slice g of plane (b,level) channel 0 ----
    {
        const int nv4 = HW / (4 * NGT);              // 160 / 40 / 10 float4 per warp
        const float4* v4 = (const float4*)pred + g * nv4;
        float fsum = 0.0f;
        for (int i = lane; i < nv4; i += 32) {
            float4 xv = v4[i];
            fsum += focal0(xv.x) + focal0(xv.y) + focal0(xv.z) + focal0(xv.w);
        }
        for (int off = 16; off; off >>= 1)
            fsum += __shfl_xor_sync(FULLMASK, fsum, off);
        if (lane == 0) g_focal[gw] = fsum;
    }
}

// ---------------- Kernel 2: deterministic parallel apply + sparse losses ----------------
__global__ void __launch_bounds__(128)
apply_kernel(const float* __restrict__ p0,
             const float* __restrict__ p1,
             const float* __restrict__ p2)
{
    __shared__ int   entCell[MAXENT];
    __shared__ int   entG[MAXENT];
    __shared__ float sBiou[NGT], sCxg[NGT], sCyg[NGT], sTwt[NGT], sTht[NGT], sFx[NGT], sFy[NGT];
    __shared__ int   sNp[NGT], sOff[NGT];
    __shared__ int   sM;
    __shared__ float red[128];

    const int bl    = blockIdx.x;
    const int b     = bl / 3;
    const int level = bl % 3;
    const float* pred = (level == 0) ? p0 : (level == 1) ? p1 : p2;
    const int W  = (level == 0) ? 160 : (level == 1) ? 80 : 40;
    const int HW = W * W;
    const float s = (level == 0) ? 0.00625f : (level == 1) ? 0.0125f : 0.025f;
    pred += (long long)b * 7 * HW;

    const int tid = threadIdx.x;

    if (tid < NGT) {
        const Stage& st = g_stage[bl * NGT + tid];
        int np = st.n_pos;
        sNp[tid]   = np;
        sBiou[tid] = st.biou;
        sCxg[tid]  = st.cxg;  sCyg[tid] = st.cyg;
        sTwt[tid]  = st.twt;  sTht[tid] = st.tht;
        sFx[tid]   = st.fx;   sFy[tid]  = st.fy;
    }
    __syncthreads();
    if (tid < NGT) {
        int off = 0;
        #pragma unroll
        for (int g2 = 0; g2 < NGT; g2++) { if (g2 < tid) off += sNp[g2]; }
        sOff[tid] = off;
        if (tid == NGT - 1) sM = off + sNp[tid];
    }
    __syncthreads();
    if (tid < NGT) {
        const Stage& st = g_stage[bl * NGT + tid];
        int off = sOff[tid];
        int np  = sNp[tid];
        for (int k = 0; k < np; k++) { entCell[off + k] = st.cells[k]; entG[off + k] = tid; }
    }
    __syncthreads();
    const int M = sM;

    // fold dense focal partials (fixed order, tid==g)
    float corr = (tid < NGT) ? g_focal[bl * NGT + tid] : 0.0f;
    float boxs = 0.0f, foots = 0.0f;
    int   nown = 0;

    for (int e = tid; e < M; e += 128) {
        int c  = entCell[e];
        int ge = entG[e];
        float z = sBiou[ge];
        bool owner = true;
        for (int e2 = 0; e2 < M; e2++) {
            if (entCell[e2] == c && e2 != e) {
                int g2 = entG[e2];
                z = fmaxf(z, sBiou[g2]);
                if (g2 > ge) owner = false;
            }
        }
        if (!owner) continue;
        nown++;

        float gxx = (float)(c % W), gyy = (float)(c / W);

        float x = pred[c];
        float prob = sigf(x);
        float l1e  = log1pf(expf(-fabsf(x)));
        float ce   = fmaxf(x, 0.0f) - x * z + l1e;
        float ce0  = fmaxf(x, 0.0f) + l1e;
        float pt   = prob * z + (1.0f - prob) * (1.0f - z);
        float at   = 0.25f * z + 0.75f * (1.0f - z);
        float om   = 1.0f - pt;
        corr += at * om * om * ce - 0.75f * prob * prob * ce0;

        float p1v = pred[HW + c], p2v = pred[2 * HW + c];
        float p3v = pred[3 * HW + c], p4v = pred[4 * HW + c];
        float pcx = (sigf(p1v) + gxx) * s;
        float pcy = (sigf(p2v) + gyy) * s;
        float pw  = expf(fminf(fmaxf(p3v, -5.0f), 5.0f)) * s;
        float ph  = expf(fminf(fmaxf(p4v, -5.0f), 5.0f)) * s;
        float tcx = sCxg[ge] * s;
        float tcy = sCyg[ge] * s;
        float tw  = expf(sTwt[ge]) * s;
        float th  = expf(sTht[ge]) * s;
        float px1 = pcx - pw * 0.5f, py1 = pcy - ph * 0.5f;
        float px2 = pcx + pw * 0.5f, py2 = pcy + ph * 0.5f;
        float qx1 = tcx - tw * 0.5f, qy1 = tcy - th * 0.5f;
        float qx2 = tcx + tw * 0.5f, qy2 = tcy + th * 0.5f;
        float iw = fmaxf(fminf(px2, qx2) - fmaxf(px1, qx1), 0.0f);
        float ih = fmaxf(fminf(py2, qy2) - fmaxf(py1, qy1), 0.0f);
        float inter = iw * ih;
        float uni = pw * ph + tw * th - inter + EPSF;
        float iou = inter / uni;
        float rho2 = (pcx - tcx) * (pcx - tcx) + (pcy - tcy) * (pcy - tcy);
        float cw  = fmaxf(px2, qx2) - fminf(px1, qx1);
        float chh = fmaxf(py2, qy2) - fminf(py1, qy1);
        float c2  = cw * cw + chh * chh + EPSF;
        float dat = atanf(tw / (th + EPSF)) - atanf(pw / (ph + EPSF));
        float v = 0.4052847345693511f * dat * dat;
        float alpha = v / (1.0f - iou + v + EPSF);
        float ciou = iou - rho2 / c2 - alpha * v;
        boxs += 1.0f - ciou;

        float p5v = pred[5 * HW + c], p6v = pred[6 * HW + c];
        float d1 = fabsf(sigf(p5v) - sFx[ge]);
        float d2 = fabsf(sigf(p6v) - sFy[ge]);
        float s1 = (d1 < 1.0f) ? 0.5f * d1 * d1 : d1 - 0.5f;
        float s2 = (d2 < 1.0f) ? 0.5f * d2 * d2 : d2 - 0.5f;
        foots += s1 + s2;
    }

    red[tid] = corr; __syncthreads();
    for (int off = 64; off; off >>= 1) { if (tid < off) red[tid] += red[tid + off]; __syncthreads(); }
    if (tid == 0) g_part[bl * 4 + 0] = red[0];
    __syncthreads();
    red[tid] = boxs; __syncthreads();
    for (int off = 64; off; off >>= 1) { if (tid < off) red[tid] += red[tid + off]; __syncthreads(); }
    if (tid == 0) g_part[bl * 4 + 1] = red[0];
    __syncthreads();
    red[tid] = foots; __syncthreads();
    for (int off = 64; off; off >>= 1) { if (tid < off) red[tid] += red[tid + off]; __syncthreads(); }
    if (tid == 0) g_part[bl * 4 + 2] = red[0];
    __syncthreads();
    red[tid] = (float)nown; __syncthreads();
    for (int off = 64; off; off >>= 1) { if (tid < off) red[tid] += red[tid + off]; __syncthreads(); }
    if (tid == 0) g_part[bl * 4 + 3] = red[0];
}

// ---------------- Kernel 3: deterministic final combine ----------------
__global__ void __launch_bounds__(256)
final_kernel(float* __restrict__ out)
{
    __shared__ float red[256];
    int t = threadIdx.x;
    float v = 0.0f;
    if (t < NBL) {
        int l = t % 3;
        float HWf = (l == 0) ? 25600.0f : (l == 1) ? 6400.0f : 1600.0f;
        float objt  = g_part[t * 4 + 0];
        float boxs  = g_part[t * 4 + 1];
        float foots = g_part[t * 4 + 2];
        float npos  = fmaxf(g_part[t * 4 + 3], 1.0f);
        v = objt / HWf + 5.0f * boxs / npos + foots / npos;
    }
    red[t] = v; __syncthreads();
    for (int o = 128; o; o >>= 1) { if (t < o) red[t] += red[t + o]; __syncthreads(); }
    if (t == 0) out[0] = red[0] / 64.0f;
}

// ---------------- launch ----------------
extern "C" void kernel_launch(void* const* d_in, const int* in_sizes, int n_in,
                              void* d_out, int out_size)
{
    const float* p0  = (const float*)d_in[0];
    const float* p1  = (const float*)d_in[1];
    const float* p2  = (const float*)d_in[2];
    const float* tgt = (const float*)d_in[3];

    stage_kernel<<<(NBL * NGT + WPB - 1) / WPB, WPB * 32>>>(p0, p1, p2, tgt);
    apply_kernel<<<NBL, 128>>>(p0, p1, p2);
    final_kernel<<<1, 256>>>((float*)d_out);
}

// round 7
// speedup vs baseline: 2.5744x; 1.0010x over previous
#include <cuda_runtime.h>
#include <math.h>

// ---------------- constants ----------------
#define MAXW     24            // max candidate-window side (scale masks bound it to <=21)
#define NGT      40
#define EPSF     1e-7f
#define FULLMASK 0xffffffffu
#define NBL      192           // 64 batches * 3 levels
#define WPB      4             // warps per block in stage kernel
#define MAXENT   400           // max entries per (b,level) = NGT*10

struct Stage {
    int   n_pos;
    int   cells[10];
    float biou, cxg, cyg, twt, tht, fx, fy;
};

__device__ Stage g_stage[NBL * NGT];
__device__ float g_focal[NBL * NGT];  // per-warp dense z=0 focal partial
__device__ float g_part[NBL * 4];     // per (b,level): obj_total, box_sum, foot_sum, npos

__device__ __forceinline__ float sigf(float x)  { return 1.0f / (1.0f + expf(-x)); }

// fast softplus(x) = max(x,0) + log1p(exp(-|x|))  -- cost-ordering only
__device__ __forceinline__ float fast_splus(float x) {
    return fmaxf(x, 0.0f) + __logf(1.0f + __expf(-fabsf(x)));
}

// fast z=0 focal term: 0.75 * sigmoid(x)^2 * softplus(x)
__device__ __forceinline__ float focal0(float x) {
    float t   = __expf(-fabsf(x));
    float inv = __fdividef(1.0f, 1.0f + t);
    float prob = (x >= 0.0f) ? inv : t * inv;
    float ce0  = fmaxf(x, 0.0f) + __logf(1.0f + t);
    return 0.75f * prob * prob * ce0;
}

// decode pred box at cell and IoU vs gt xyxy -- precise math (feeds floor/n_pos/z)
__device__ __forceinline__ float pred_iou(const float* __restrict__ pred, int HW, int cell,
                                          float gxx, float gyy, float s,
                                          float tx1, float ty1, float tx2, float ty2, float tA)
{
    float p1 = pred[HW + cell];
    float p2 = pred[2 * HW + cell];
    float p3 = pred[3 * HW + cell];
    float p4 = pred[4 * HW + cell];
    float pcx = (sigf(p1) + gxx) * s;
    float pcy = (sigf(p2) + gyy) * s;
    float pw  = expf(fminf(fmaxf(p3, -5.0f), 5.0f)) * s;
    float ph  = expf(fminf(fmaxf(p4, -5.0f), 5.0f)) * s;
    float px1 = pcx - pw * 0.5f, py1 = pcy - ph * 0.5f;
    float px2 = pcx + pw * 0.5f, py2 = pcy + ph * 0.5f;
    float iw = fmaxf(fminf(px2, tx2) - fmaxf(px1, tx1), 0.0f);
    float ih = fmaxf(fminf(py2, ty2) - fmaxf(py1, ty1), 0.0f);
    float inter = iw * ih;
    float aa = (px2 - px1) * (py2 - py1);
    return inter / (aa + tA - inter + EPSF);
}

// ---------------- Kernel 1: per-GT selection (register top-10) + fused dense focal ----------------
__global__ void __launch_bounds__(WPB * 32, 8)
stage_kernel(const float* __restrict__ p0,
             const float* __restrict__ p1,
             const float* __restrict__ p2,
             const float* __restrict__ tgt)
{
    const int lane = threadIdx.x & 31;
    const int wloc = threadIdx.x >> 5;
    const int gw   = blockIdx.x * WPB + wloc;
    if (gw >= NBL * NGT) return;

    const int bl    = gw / NGT;
    const int g     = gw - bl * NGT;
    const int b     = bl / 3;
    const int level = bl % 3;

    const float* predB = (level == 0) ? p0 : (level == 1) ? p1 : p2;
    const int W  = (level == 0) ? 160 : (level == 1) ? 80 : 40;
    const int HW = W * W;
    const float s = (level == 0) ? 0.00625f : (level == 1) ? 0.0125f : 0.025f;
    const float* pred = predB + (long long)b * 7 * HW;

    Stage& st = g_stage[gw];

    const float* t = &tgt[b * NGT * 7 + g * 7];
    float cls = t[0], cx = t[1], cy = t[2], w = t[3], h = t[4], fx = t[5], fy = t[6];
    float size = fmaxf(w, h) * 1280.0f;
    bool valid = (cls == 0.0f) &&
                 ((level == 0) ? (size < 128.0f)
                  : (level == 1) ? (size >= 48.0f && size < 288.0f)
                                 : (size >= 128.0f));

    const float INF = __int_as_float(0x7f800000);

    if (!valid) {
        if (lane == 0) st.n_pos = 0;
    } else {
        float cxg = cx / s, cyg = cy / s;
        float x1b = (cx - w * 0.5f) / s, x2b = (cx + w * 0.5f) / s;
        float y1b = (cy - h * 0.5f) / s, y2b = (cy + h * 0.5f) / s;
        float tx1 = cx - w * 0.5f, ty1 = cy - h * 0.5f;
        float tx2 = cx + w * 0.5f, ty2 = cy + h * 0.5f;
        float tA  = (tx2 - tx1) * (ty2 - ty1);

        int gx0 = max(0, (int)floorf(fminf(cxg - 2.5f, x1b)));
        int gx1 = min(W - 1, (int)ceilf(fmaxf(cxg + 2.5f, x2b)));
        int gy0 = max(0, (int)floorf(fminf(cyg - 2.5f, y1b)));
        int gy1 = min(W - 1, (int)ceilf(fmaxf(cyg + 2.5f, y2b)));
        int wx = gx1 - gx0 + 1, wy = gy1 - gy0 + 1;
        if (wx > MAXW) wx = MAXW;
        if (wy > MAXW) wy = MAXW;
        int nwin = (wx > 0 && wy > 0) ? wx * wy : 0;

        // per-lane sorted top-10 (cost asc, tie -> earlier slot first)
        float lc[10];
        int   ls[10];
        #pragma unroll
        for (int i = 0; i < 10; i++) { lc[i] = INF; ls[i] = 0x7fffffff; }

        float lis = 0.0f;
        int   lnc = 0;
        for (int si = lane; si < nwin; si += 32) {
            int iy = si / wx, ix = si - iy * wx;
            float gxx = (float)(gx0 + ix), gyy = (float)(gy0 + iy);
            bool ic = (fabsf(gxx - cxg) < 2.5f) && (fabsf(gyy - cyg) < 2.5f);
            bool ib = (gxx >= x1b) && (gxx < x2b) && (gyy >= y1b) && (gyy < y2b);
            if (ic || ib) {
                int cell = (gy0 + iy) * W + (gx0 + ix);
                float iou  = pred_iou(pred, HW, cell, gxx, gyy, s, tx1, ty1, tx2, ty2, tA);
                float p0v  = pred[cell];
                float c = fast_splus(-p0v) - 3.0f * __logf(iou + EPSF);
                lis += iou;
                lnc += 1;
                if (c < lc[9]) {   // bubble-insert; strict < keeps earlier slot first on ties
                    lc[9] = c; ls[9] = si;
                    #pragma unroll
                    for (int i = 9; i > 0; i--) {
                        if (lc[i] < lc[i - 1]) {
                            float tc = lc[i]; lc[i] = lc[i - 1]; lc[i - 1] = tc;
                            int   ts = ls[i]; ls[i] = ls[i - 1]; ls[i - 1] = ts;
                        }
                    }
                }
            }
        }
        for (int off = 16; off; off >>= 1) {
            lis += __shfl_xor_sync(FULLMASK, lis, off);
            lnc += __shfl_xor_sync(FULLMASK, lnc, off);
        }

        int n_pos;
        float best_iou = 0.0f;
        if (lnc == 0) {
            // fallback: nearest cell (full plane), tie -> smaller index
            float bd = INF; int bc = 0x7fffffff;
            for (int cell = lane; cell < HW; cell += 32) {
                float gxx = (float)(cell % W), gyy = (float)(cell / W);
                float d = (gxx - cxg) * (gxx - cxg) + (gyy - cyg) * (gyy - cyg);
                if (d < bd) { bd = d; bc = cell; }
            }
            for (int off = 16; off; off >>= 1) {
                float od = __shfl_xor_sync(FULLMASK, bd, off);
                int   oc = __shfl_xor_sync(FULLMASK, bc, off);
                if (od < bd || (od == bd && oc < bc)) { bd = od; bc = oc; }
            }
            n_pos = 1;
            float gxx = (float)(bc % W), gyy = (float)(bc / W);
            best_iou = pred_iou(pred, HW, bc, gxx, gyy, s, tx1, ty1, tx2, ty2, tA);
            if (lane == 0) st.cells[0] = bc;
        } else {
            int hi = min(10, lnc);
            int fl = (int)floorf(lis);
            n_pos = min(hi, max(1, fl));
            for (int k = 0; k < n_pos; k++) {
                // warp argmin over per-lane heads (lexicographic on (cost, slot))
                float hc = lc[0]; int hs = ls[0];
                for (int off = 16; off; off >>= 1) {
                    float oc = __shfl_xor_sync(FULLMASK, hc, off);
                    int   os = __shfl_xor_sync(FULLMASK, hs, off);
                    if (oc < hc || (oc == hc && os < hs)) { hc = oc; hs = os; }
                }
                int iy = hs / wx, ix = hs - iy * wx;
                int cell = (gy0 + iy) * W + (gx0 + ix);
                if (k == 0) {
                    float gxx = (float)(gx0 + ix), gyy = (float)(gy0 + iy);
                    best_iou = pred_iou(pred, HW, cell, gxx, gyy, s, tx1, ty1, tx2, ty2, tA);
                }
                if (lane == 0) st.cells[k] = cell;
                // winner lane pops its head
                if (lc[0] == hc && ls[0] == hs) {
                    #pragma unroll
                    for (int i = 0; i < 9; i++) { lc[i] = lc[i + 1]; ls[i] = ls[i + 1]; }
                    lc[9] = INF; ls[9] = 0x7fffffff;
                }
            }
        }
        if (lane == 0) {
            st.n_pos = n_pos;
            st.biou  = best_iou;
            st.cxg = cxg; st.cyg = cyg;
            st.twt = logf(w / s + EPSF);
            st.tht = logf(h / s + EPSF);
            st.fx = fx; st.fy = fy;
        }
    }

    // ---- fused dense z=0 focal: warp g handles slice g of plane (b,level) channel 0 ----
    {
        const int nv4 = HW / (4 * NGT);              // 160 / 40 / 10 float4 per warp
        const float4* v4 = (const float4*)pred + g * nv4;
        float fsum = 0.0f;
        for (int i = lane; i < nv4; i += 32) {
            float4 xv = v4[i];
            fsum += focal0(xv.x) + focal0(xv.y) + focal0(xv.z) + focal0(xv.w);
        }
        for (int off = 16; off; off >>= 1)
            fsum += __shfl_xor_sync(FULLMASK, fsum, off);
        if (lane == 0) g_focal[gw] = fsum;
    }
}

// ---------------- Kernel 2: deterministic parallel apply + sparse losses ----------------
__global__ void __launch_bounds__(128)
apply_kernel(const float* __restrict__ p0,
             const float* __restrict__ p1,
             const float* __restrict__ p2)
{
    __shared__ int   entCell[MAXENT];
    __shared__ int   entG[MAXENT];
    __shared__ float sBiou[NGT], sCxg[NGT], sCyg[NGT], sTwt[NGT], sTht[NGT], sFx[NGT], sFy[NGT];
    __shared__ int   sNp[NGT], sOff[NGT];
    __shared__ int   sM;
    __shared__ float red[128];

    const int bl    = blockIdx.x;
    const int b     = bl / 3;
    const int level = bl % 3;
    const float* pred = (level == 0) ? p0 : (level == 1) ? p1 : p2;
    const int W  = (level == 0) ? 160 : (level == 1) ? 80 : 40;
    const int HW = W * W;
    const float s = (level == 0) ? 0.00625f : (level == 1) ? 0.0125f : 0.025f;
    pred += (long long)b * 7 * HW;

    const int tid = threadIdx.x;

    if (tid < NGT) {
        const Stage& st = g_stage[bl * NGT + tid];
        int np = st.n_pos;
        sNp[tid]   = np;
        sBiou[tid] = st.biou;
        sCxg[tid]  = st.cxg;  sCyg[tid] = st.cyg;
        sTwt[tid]  = st.twt;  sTht[tid] = st.tht;
        sFx[tid]   = st.fx;   sFy[tid]  = st.fy;
    }
    __syncthreads();
    if (tid < NGT) {
        int off = 0;
        #pragma unroll
        for (int g2 = 0; g2 < NGT; g2++) { if (g2 < tid) off += sNp[g2]; }
        sOff[tid] = off;
        if (tid == NGT - 1) sM = off + sNp[tid];
    }
    __syncthreads();
    if (tid < NGT) {
        const Stage& st = g_stage[bl * NGT + tid];
        int off = sOff[tid];
        int np  = sNp[tid];
        for (int k = 0; k < np; k++) { entCell[off + k] = st.cells[k]; entG[off + k] = tid; }
    }
    __syncthreads();
    const int M = sM;

    // fold dense focal partials (fixed order, tid==g)
    float corr = (tid < NGT) ? g_focal[bl * NGT + tid] : 0.0f;
    float boxs = 0.0f, foots = 0.0f;
    int   nown = 0;

    for (int e = tid; e < M; e += 128) {
        int c  = entCell[e];
        int ge = entG[e];
        float z = sBiou[ge];
        bool owner = true;
        for (int e2 = 0; e2 < M; e2++) {
            if (entCell[e2] == c && e2 != e) {
                int g2 = entG[e2];
                z = fmaxf(z, sBiou[g2]);
                if (g2 > ge) owner = false;
            }
        }
        if (!owner) continue;
        nown++;

        float gxx = (float)(c % W), gyy = (float)(c / W);

        float x = pred[c];
        float prob = sigf(x);
        float l1e  = log1pf(expf(-fabsf(x)));
        float ce   = fmaxf(x, 0.0f) - x * z + l1e;
        float ce0  = fmaxf(x, 0.0f) + l1e;
        float pt   = prob * z + (1.0f - prob) * (1.0f - z);
        float at   = 0.25f * z + 0.75f * (1.0f - z);
        float om   = 1.0f - pt;
        corr += at * om * om * ce - 0.75f * prob * prob * ce0;

        float p1v = pred[HW + c], p2v = pred[2 * HW + c];
        float p3v = pred[3 * HW + c], p4v = pred[4 * HW + c];
        float pcx = (sigf(p1v) + gxx) * s;
        float pcy = (sigf(p2v) + gyy) * s;
        float pw  = expf(fminf(fmaxf(p3v, -5.0f), 5.0f)) * s;
        float ph  = expf(fminf(fmaxf(p4v, -5.0f), 5.0f)) * s;
        float tcx = sCxg[ge] * s;
        float tcy = sCyg[ge] * s;
        float tw  = expf(sTwt[ge]) * s;
        float th  = expf(sTht[ge]) * s;
        float px1 = pcx - pw * 0.5f, py1 = pcy - ph * 0.5f;
        float px2 = pcx + pw * 0.5f, py2 = pcy + ph * 0.5f;
        float qx1 = tcx - tw * 0.5f, qy1 = tcy - th * 0.5f;
        float qx2 = tcx + tw * 0.5f, qy2 = tcy + th * 0.5f;
        float iw = fmaxf(fminf(px2, qx2) - fmaxf(px1, qx1), 0.0f);
        float ih = fmaxf(fminf(py2, qy2) - fmaxf(py1, qy1), 0.0f);
        float inter = iw * ih;
        float uni = pw * ph + tw * th - inter + EPSF;
        float iou = inter / uni;
        float rho2 = (pcx - tcx) * (pcx - tcx) + (pcy - tcy) * (pcy - tcy);
        float cw  = fmaxf(px2, qx2) - fminf(px1, qx1);
        float chh = fmaxf(py2, qy2) - fminf(py1, qy1);
        float c2  = cw * cw + chh * chh + EPSF;
        float dat = atanf(tw / (th + EPSF)) - atanf(pw / (ph + EPSF));
        float v = 0.4052847345693511f * dat * dat;
        float alpha = v / (1.0f - iou + v + EPSF);
        float ciou = iou - rho2 / c2 - alpha * v;
        boxs += 1.0f - ciou;

        float p5v = pred[5 * HW + c], p6v = pred[6 * HW + c];
        float d1 = fabsf(sigf(p5v) - sFx[ge]);
        float d2 = fabsf(sigf(p6v) - sFy[ge]);
        float s1 = (d1 < 1.0f) ? 0.5f * d1 * d1 : d1 - 0.5f;
        float s2 = (d2 < 1.0f) ? 0.5f * d2 * d2 : d2 - 0.5f;
        foots += s1 + s2;
    }

    red[tid] = corr; __syncthreads();
    for (int off = 64; off; off >>= 1) { if (tid < off) red[tid] += red[tid + off]; __syncthreads(); }
    if (tid == 0) g_part[bl * 4 + 0] = red[0];
    __syncthreads();
    red[tid] = boxs; __syncthreads();
    for (int off = 64; off; off >>= 1) { if (tid < off) red[tid] += red[tid + off]; __syncthreads(); }
    if (tid == 0) g_part[bl * 4 + 1] = red[0];
    __syncthreads();
    red[tid] = foots; __syncthreads();
    for (int off = 64; off; off >>= 1) { if (tid < off) red[tid] += red[tid + off]; __syncthreads(); }
    if (tid == 0) g_part[bl * 4 + 2] = red[0];
    __syncthreads();
    red[tid] = (float)nown; __syncthreads();
    for (int off = 64; off; off >>= 1) { if (tid < off) red[tid] += red[tid + off]; __syncthreads(); }
    if (tid == 0) g_part[bl * 4 + 3] = red[0];
}

// ---------------- Kernel 3: deterministic final combine ----------------
__global__ void __launch_bounds__(256)
final_kernel(float* __restrict__ out)
{
    __shared__ float red[256];
    int t = threadIdx.x;
    float v = 0.0f;
    if (t < NBL) {
        int l = t % 3;
        float HWf = (l == 0) ? 25600.0f : (l == 1) ? 6400.0f : 1600.0f;
        float objt  = g_part[t * 4 + 0];
        float boxs  = g_part[t * 4 + 1];
        float foots = g_part[t * 4 + 2];
        float npos  = fmaxf(g_part[t * 4 + 3], 1.0f);
        v = objt / HWf + 5.0f * boxs / npos + foots / npos;
    }
    red[t] = v; __syncthreads();
    for (int o = 128; o; o >>= 1) { if (t < o) red[t] += red[t + o]; __syncthreads(); }
    if (t == 0) out[0] = red[0] / 64.0f;
}

// ---------------- launch ----------------
extern "C" void kernel_launch(void* const* d_in, const int* in_sizes, int n_in,
                              void* d_out, int out_size)
{
    const float* p0  = (const float*)d_in[0];
    const float* p1  = (const float*)d_in[1];
    const float* p2  = (const float*)d_in[2];
    const float* tgt = (const float*)d_in[3];

    stage_kernel<<<(NBL * NGT + WPB - 1) / WPB, WPB * 32>>>(p0, p1, p2, tgt);
    apply_kernel<<<NBL, 128>>>(p0, p1, p2);
    final_kernel<<<1, 256>>>((float*)d_out);
}

// round 8
// speedup vs baseline: 2.5903x; 1.0062x over previous
#include <cuda_runtime.h>
#include <math.h>

// ---------------- constants ----------------
#define MAXW     24            // max candidate-window side (scale masks bound it to <=21)
#define NGT      40
#define EPSF     1e-7f
#define FULLMASK 0xffffffffu
#define NBL      192           // 64 batches * 3 levels
#define MAXENT   400           // max entries per (b,level) = NGT*10
#define KMAX     5             // ceil(576 / 128)

struct Stage {
    int   n_pos;
    int   cells[10];
    float biou, cxg, cyg, twt, tht, fx, fy;
};

__device__ Stage g_stage[NBL * NGT];
__device__ float g_focal[NBL * NGT];  // per-block dense z=0 focal partial
__device__ float g_part[NBL * 4];     // per (b,level): obj_total, box_sum, foot_sum, npos

__device__ __forceinline__ float sigf(float x)  { return 1.0f / (1.0f + expf(-x)); }

// fast softplus -- cost-ordering only
__device__ __forceinline__ float fast_splus(float x) {
    return fmaxf(x, 0.0f) + __logf(1.0f + __expf(-fabsf(x)));
}

// fast z=0 focal term: 0.75 * sigmoid(x)^2 * softplus(x)
__device__ __forceinline__ float focal0(float x) {
    float t   = __expf(-fabsf(x));
    float inv = __fdividef(1.0f, 1.0f + t);
    float prob = (x >= 0.0f) ? inv : t * inv;
    float ce0  = fmaxf(x, 0.0f) + __logf(1.0f + t);
    return 0.75f * prob * prob * ce0;
}

// IoU from already-loaded channel values (precise math; feeds floor/n_pos/z)
__device__ __forceinline__ float iou_vals(float p1, float p2, float p3, float p4,
                                          float gxx, float gyy, float s,
                                          float tx1, float ty1, float tx2, float ty2, float tA)
{
    float pcx = (sigf(p1) + gxx) * s;
    float pcy = (sigf(p2) + gyy) * s;
    float pw  = expf(fminf(fmaxf(p3, -5.0f), 5.0f)) * s;
    float ph  = expf(fminf(fmaxf(p4, -5.0f), 5.0f)) * s;
    float px1 = pcx - pw * 0.5f, py1 = pcy - ph * 0.5f;
    float px2 = pcx + pw * 0.5f, py2 = pcy + ph * 0.5f;
    float iw = fmaxf(fminf(px2, tx2) - fmaxf(px1, tx1), 0.0f);
    float ih = fmaxf(fminf(py2, ty2) - fmaxf(py1, ty1), 0.0f);
    float inter = iw * ih;
    float aa = (px2 - px1) * (py2 - py1);
    return inter / (aa + tA - inter + EPSF);
}

__device__ __forceinline__ float pred_iou(const float* __restrict__ pred, int HW, int cell,
                                          float gxx, float gyy, float s,
                                          float tx1, float ty1, float tx2, float ty2, float tA)
{
    return iou_vals(pred[HW + cell], pred[2 * HW + cell], pred[3 * HW + cell], pred[4 * HW + cell],
                    gxx, gyy, s, tx1, ty1, tx2, ty2, tA);
}

// ---------------- Kernel 1: one block per (b,level,gt) ----------------
__global__ void __launch_bounds__(128)
stage_kernel(const float* __restrict__ p0,
             const float* __restrict__ p1,
             const float* __restrict__ p2,
             const float* __restrict__ tgt)
{
    __shared__ float sc[10][4];
    __shared__ int   ss[10][4];
    __shared__ float rls[4];
    __shared__ int   rlc[4];
    __shared__ float red[128];

    const int tid  = threadIdx.x;
    const int lane = tid & 31;
    const int wid  = tid >> 5;

    const int gw    = blockIdx.x;
    const int bl    = gw / NGT;
    const int g     = gw - bl * NGT;
    const int b     = bl / 3;
    const int level = bl % 3;

    const float* predB = (level == 0) ? p0 : (level == 1) ? p1 : p2;
    const int W  = (level == 0) ? 160 : (level == 1) ? 80 : 40;
    const int HW = W * W;
    const float s = (level == 0) ? 0.00625f : (level == 1) ? 0.0125f : 0.025f;
    const float* pred = predB + (long long)b * 7 * HW;

    Stage& st = g_stage[gw];

    // ---- fused dense z=0 focal slice (independent loads, issued early) ----
    float fsum = 0.0f;
    {
        const int nv4 = HW / (4 * NGT);              // 160 / 40 / 10 float4 per block
        const float4* v4 = (const float4*)pred + g * nv4;
        for (int i = tid; i < nv4; i += 128) {
            float4 xv = v4[i];
            fsum += focal0(xv.x) + focal0(xv.y) + focal0(xv.z) + focal0(xv.w);
        }
    }

    // ---- target (broadcast load) ----
    const float* t = &tgt[b * NGT * 7 + g * 7];
    float cls = t[0], cx = t[1], cy = t[2], w = t[3], h = t[4], fx = t[5], fy = t[6];
    float size = fmaxf(w, h) * 1280.0f;
    bool valid = (cls == 0.0f) &&
                 ((level == 0) ? (size < 128.0f)
                  : (level == 1) ? (size >= 48.0f && size < 288.0f)
                                 : (size >= 128.0f));

    const float INF = __int_as_float(0x7f800000);

    if (valid) {
        float cxg = cx / s, cyg = cy / s;
        float x1b = (cx - w * 0.5f) / s, x2b = (cx + w * 0.5f) / s;
        float y1b = (cy - h * 0.5f) / s, y2b = (cy + h * 0.5f) / s;
        float tx1 = cx - w * 0.5f, ty1 = cy - h * 0.5f;
        float tx2 = cx + w * 0.5f, ty2 = cy + h * 0.5f;
        float tA  = (tx2 - tx1) * (ty2 - ty1);

        int gx0 = max(0, (int)floorf(fminf(cxg - 2.5f, x1b)));
        int gx1 = min(W - 1, (int)ceilf(fmaxf(cxg + 2.5f, x2b)));
        int gy0 = max(0, (int)floorf(fminf(cyg - 2.5f, y1b)));
        int gy1 = min(W - 1, (int)ceilf(fmaxf(cyg + 2.5f, y2b)));
        int wx = gx1 - gx0 + 1, wy = gy1 - gy0 + 1;
        if (wx > MAXW) wx = MAXW;
        if (wy > MAXW) wy = MAXW;
        int nwin = (wx > 0 && wy > 0) ? wx * wy : 0;

        // ---- pass 1: issue ALL window loads (up to KMAX iterations) ----
        float v0[KMAX], v1[KMAX], v2[KMAX], v3[KMAX], v4c[KMAX];
        bool  act[KMAX];
        #pragma unroll
        for (int k = 0; k < KMAX; k++) {
            int si = tid + k * 128;
            act[k] = false;
            if (si < nwin) {
                int iy = si / wx, ix = si - iy * wx;
                float gxx = (float)(gx0 + ix), gyy = (float)(gy0 + iy);
                bool ic = (fabsf(gxx - cxg) < 2.5f) && (fabsf(gyy - cyg) < 2.5f);
                bool ib = (gxx >= x1b) && (gxx < x2b) && (gyy >= y1b) && (gyy < y2b);
                if (ic || ib) {
                    act[k] = true;
                    int cell = (gy0 + iy) * W + (gx0 + ix);
                    v0[k] = pred[cell];
                    v1[k] = pred[HW + cell];
                    v2[k] = pred[2 * HW + cell];
                    v3[k] = pred[3 * HW + cell];
                    v4c[k] = pred[4 * HW + cell];
                }
            }
        }

        // per-lane sorted top-10 (cost asc, tie -> earlier slot)
        float lc[10];
        int   ls[10];
        #pragma unroll
        for (int i = 0; i < 10; i++) { lc[i] = INF; ls[i] = 0x7fffffff; }

        float lis = 0.0f;
        int   lnc = 0;
        #pragma unroll
        for (int k = 0; k < KMAX; k++) {
            if (!act[k]) continue;
            int si = tid + k * 128;
            int iy = si / wx, ix = si - iy * wx;
            float gxx = (float)(gx0 + ix), gyy = (float)(gy0 + iy);
            float iou = iou_vals(v1[k], v2[k], v3[k], v4c[k], gxx, gyy, s, tx1, ty1, tx2, ty2, tA);
            float c = fast_splus(-v0[k]) - 3.0f * __logf(iou + EPSF);
            lis += iou;
            lnc += 1;
            if (c < lc[9]) {
                lc[9] = c; ls[9] = si;
                #pragma unroll
                for (int i = 9; i > 0; i--) {
                    if (lc[i] < lc[i - 1]) {
                        float tc = lc[i]; lc[i] = lc[i - 1]; lc[i - 1] = tc;
                        int   ts = ls[i]; ls[i] = ls[i - 1]; ls[i - 1] = ts;
                    }
                }
            }
        }

        // block reduce lis / lnc (deterministic: butterfly + fixed 4-term sum)
        for (int off = 16; off; off >>= 1) {
            lis += __shfl_xor_sync(FULLMASK, lis, off);
            lnc += __shfl_xor_sync(FULLMASK, lnc, off);
        }
        if (lane == 0) { rls[wid] = lis; rlc[wid] = lnc; }
        __syncthreads();
        lis = rls[0] + rls[1] + rls[2] + rls[3];
        lnc = rlc[0] + rlc[1] + rlc[2] + rlc[3];

        if (lnc == 0) {
            // fallback (practically unreachable): nearest cell, warp 0 only
            if (wid == 0) {
                float bd = INF; int bc = 0x7fffffff;
                for (int cell = lane; cell < HW; cell += 32) {
                    float gxx = (float)(cell % W), gyy = (float)(cell / W);
                    float d = (gxx - cxg) * (gxx - cxg) + (gyy - cyg) * (gyy - cyg);
                    if (d < bd) { bd = d; bc = cell; }
                }
                for (int off = 16; off; off >>= 1) {
                    float od = __shfl_xor_sync(FULLMASK, bd, off);
                    int   oc = __shfl_xor_sync(FULLMASK, bc, off);
                    if (od < bd || (od == bd && oc < bc)) { bd = od; bc = oc; }
                }
                if (lane == 0) {
                    float gxx = (float)(bc % W), gyy = (float)(bc / W);
                    st.cells[0] = bc;
                    st.n_pos = 1;
                    st.biou  = pred_iou(pred, HW, bc, gxx, gyy, s, tx1, ty1, tx2, ty2, tA);
                    st.cxg = cxg; st.cyg = cyg;
                    st.twt = logf(w / s + EPSF);
                    st.tht = logf(h / s + EPSF);
                    st.fx = fx; st.fy = fy;
                }
            }
        } else {
            int n_pos = min(min(10, lnc), max(1, (int)floorf(lis)));
            int cell0 = 0;
            for (int k = 0; k < n_pos; k++) {
                // block lexmin over per-lane heads
                float hc = lc[0]; int hs = ls[0];
                for (int off = 16; off; off >>= 1) {
                    float oc = __shfl_xor_sync(FULLMASK, hc, off);
                    int   os = __shfl_xor_sync(FULLMASK, hs, off);
                    if (oc < hc || (oc == hc && os < hs)) { hc = oc; hs = os; }
                }
                if (lane == 0) { sc[k][wid] = hc; ss[k][wid] = hs; }
                __syncthreads();
                float bc2 = sc[k][0]; int bs2 = ss[k][0];
                #pragma unroll
                for (int j = 1; j < 4; j++) {
                    float oc = sc[k][j]; int os = ss[k][j];
                    if (oc < bc2 || (oc == bc2 && os < bs2)) { bc2 = oc; bs2 = os; }
                }
                int iy = bs2 / wx, ix = bs2 - iy * wx;
                int cell = (gy0 + iy) * W + (gx0 + ix);
                if (k == 0) cell0 = cell;
                if (tid == 0) st.cells[k] = cell;
                // owner lane pops (slots unique -> exactly one lane)
                if (lc[0] == bc2 && ls[0] == bs2) {
                    #pragma unroll
                    for (int i = 0; i < 9; i++) { lc[i] = lc[i + 1]; ls[i] = ls[i + 1]; }
                    lc[9] = INF; ls[9] = 0x7fffffff;
                }
            }
            if (tid == 0) {
                float gxx = (float)(cell0 % W), gyy = (float)(cell0 / W);
                st.n_pos = n_pos;
                st.biou  = pred_iou(pred, HW, cell0, gxx, gyy, s, tx1, ty1, tx2, ty2, tA);
                st.cxg = cxg; st.cyg = cyg;
                st.twt = logf(w / s + EPSF);
                st.tht = logf(h / s + EPSF);
                st.fx = fx; st.fy = fy;
            }
        }
    } else {
        if (tid == 0) st.n_pos = 0;
    }
    __syncthreads();

    // ---- focal block reduce (deterministic tree) ----
    red[tid] = fsum; __syncthreads();
    for (int off = 64; off; off >>= 1) { if (tid < off) red[tid] += red[tid + off]; __syncthreads(); }
    if (tid == 0) g_focal[gw] = red[0];
}

// ---------------- Kernel 2: deterministic parallel apply + sparse losses ----------------
__global__ void __launch_bounds__(128)
apply_kernel(const float* __restrict__ p0,
             const float* __restrict__ p1,
             const float* __restrict__ p2)
{
    __shared__ int   entCell[MAXENT];
    __shared__ int   entG[MAXENT];
    __shared__ float sBiou[NGT], sCxg[NGT], sCyg[NGT], sTwt[NGT], sTht[NGT], sFx[NGT], sFy[NGT];
    __shared__ int   sNp[NGT], sOff[NGT];
    __shared__ int   sM;
    __shared__ float red[128];

    const int bl    = blockIdx.x;
    const int b     = bl / 3;
    const int level = bl % 3;
    const float* pred = (level == 0) ? p0 : (level == 1) ? p1 : p2;
    const int W  = (level == 0) ? 160 : (level == 1) ? 80 : 40;
    const int HW = W * W;
    const float s = (level == 0) ? 0.00625f : (level == 1) ? 0.0125f : 0.025f;
    pred += (long long)b * 7 * HW;

    const int tid = threadIdx.x;

    if (tid < NGT) {
        const Stage& st = g_stage[bl * NGT + tid];
        int np = st.n_pos;
        sNp[tid]   = np;
        sBiou[tid] = st.biou;
        sCxg[tid]  = st.cxg;  sCyg[tid] = st.cyg;
        sTwt[tid]  = st.twt;  sTht[tid] = st.tht;
        sFx[tid]   = st.fx;   sFy[tid]  = st.fy;
    }
    __syncthreads();
    if (tid < NGT) {
        int off = 0;
        #pragma unroll
        for (int g2 = 0; g2 < NGT; g2++) { if (g2 < tid) off += sNp[g2]; }
        sOff[tid] = off;
        if (tid == NGT - 1) sM = off + sNp[tid];
    }
    __syncthreads();
    if (tid < NGT) {
        const Stage& st = g_stage[bl * NGT + tid];
        int off = sOff[tid];
        int np  = sNp[tid];
        for (int k = 0; k < np; k++) { entCell[off + k] = st.cells[k]; entG[off + k] = tid; }
    }
    __syncthreads();
    const int M = sM;

    // fold dense focal partials (fixed order, tid==g)
    float corr = (tid < NGT) ? g_focal[bl * NGT + tid] : 0.0f;
    float boxs = 0.0f, foots = 0.0f;
    int   nown = 0;

    for (int e = tid; e < M; e += 128) {
        int c  = entCell[e];
        int ge = entG[e];
        float z = sBiou[ge];
        bool owner = true;
        for (int e2 = 0; e2 < M; e2++) {
            if (entCell[e2] == c && e2 != e) {
                int g2 = entG[e2];
                z = fmaxf(z, sBiou[g2]);
                if (g2 > ge) owner = false;
            }
        }
        if (!owner) continue;
        nown++;

        float gxx = (float)(c % W), gyy = (float)(c / W);

        float x = pred[c];
        float prob = sigf(x);
        float l1e  = log1pf(expf(-fabsf(x)));
        float ce   = fmaxf(x, 0.0f) - x * z + l1e;
        float ce0  = fmaxf(x, 0.0f) + l1e;
        float pt   = prob * z + (1.0f - prob) * (1.0f - z);
        float at   = 0.25f * z + 0.75f * (1.0f - z);
        float om   = 1.0f - pt;
        corr += at * om * om * ce - 0.75f * prob * prob * ce0;

        float p1v = pred[HW + c], p2v = pred[2 * HW + c];
        float p3v = pred[3 * HW + c], p4v = pred[4 * HW + c];
        float pcx = (sigf(p1v) + gxx) * s;
        float pcy = (sigf(p2v) + gyy) * s;
        float pw  = expf(fminf(fmaxf(p3v, -5.0f), 5.0f)) * s;
        float ph  = expf(fminf(fmaxf(p4v, -5.0f), 5.0f)) * s;
        float tcx = sCxg[ge] * s;
        float tcy = sCyg[ge] * s;
        float tw  = expf(sTwt[ge]) * s;
        float th  = expf(sTht[ge]) * s;
        float px1 = pcx - pw * 0.5f, py1 = pcy - ph * 0.5f;
        float px2 = pcx + pw * 0.5f, py2 = pcy + ph * 0.5f;
        float qx1 = tcx - tw * 0.5f, qy1 = tcy - th * 0.5f;
        float qx2 = tcx + tw * 0.5f, qy2 = tcy + th * 0.5f;
        float iw = fmaxf(fminf(px2, qx2) - fmaxf(px1, qx1), 0.0f);
        float ih = fmaxf(fminf(py2, qy2) - fmaxf(py1, qy1), 0.0f);
        float inter = iw * ih;
        float uni = pw * ph + tw * th - inter + EPSF;
        float iou = inter / uni;
        float rho2 = (pcx - tcx) * (pcx - tcx) + (pcy - tcy) * (pcy - tcy);
        float cw  = fmaxf(px2, qx2) - fminf(px1, qx1);
        float chh = fmaxf(py2, qy2) - fminf(py1, qy1);
        float c2  = cw * cw + chh * chh + EPSF;
        float dat = atanf(tw / (th + EPSF)) - atanf(pw / (ph + EPSF));
        float v = 0.4052847345693511f * dat * dat;
        float alpha = v / (1.0f - iou + v + EPSF);
        float ciou = iou - rho2 / c2 - alpha * v;
        boxs += 1.0f - ciou;

        float p5v = pred[5 * HW + c], p6v = pred[6 * HW + c];
        float d1 = fabsf(sigf(p5v) - sFx[ge]);
        float d2 = fabsf(sigf(p6v) - sFy[ge]);
        float s1 = (d1 < 1.0f) ? 0.5f * d1 * d1 : d1 - 0.5f;
        float s2 = (d2 < 1.0f) ? 0.5f * d2 * d2 : d2 - 0.5f;
        foots += s1 + s2;
    }

    red[tid] = corr; __syncthreads();
    for (int off = 64; off; off >>= 1) { if (tid < off) red[tid] += red[tid + off]; __syncthreads(); }
    if (tid == 0) g_part[bl * 4 + 0] = red[0];
    __syncthreads();
    red[tid] = boxs; __syncthreads();
    for (int off = 64; off; off >>= 1) { if (tid < off) red[tid] += red[tid + off]; __syncthreads(); }
    if (tid == 0) g_part[bl * 4 + 1] = red[0];
    __syncthreads();
    red[tid] = foots; __syncthreads();
    for (int off = 64; off; off >>= 1) { if (tid < off) red[tid] += red[tid + off]; __syncthreads(); }
    if (tid == 0) g_part[bl * 4 + 2] = red[0];
    __syncthreads();
    red[tid] = (float)nown; __syncthreads();
    for (int off = 64; off; off >>= 1) { if (tid < off) red[tid] += red[tid + off]; __syncthreads(); }
    if (tid == 0) g_part[bl * 4 + 3] = red[0];
}

// ---------------- Kernel 3: deterministic final combine ----------------
__global__ void __launch_bounds__(256)
final_kernel(float* __restrict__ out)
{
    __shared__ float red[256];
    int t = threadIdx.x;
    float v = 0.0f;
    if (t < NBL) {
        int l = t % 3;
        float HWf = (l == 0) ? 25600.0f : (l == 1) ? 6400.0f : 1600.0f;
        float objt  = g_part[t * 4 + 0];
        float boxs  = g_part[t * 4 + 1];
        float foots = g_part[t * 4 + 2];
        float npos  = fmaxf(g_part[t * 4 + 3], 1.0f);
        v = objt / HWf + 5.0f * boxs / npos + foots / npos;
    }
    red[t] = v; __syncthreads();
    for (int o = 128; o; o >>= 1) { if (t < o) red[t] += red[t + o]; __syncthreads(); }
    if (t == 0) out[0] = red[0] / 64.0f;
}

// ---------------- launch ----------------
extern "C" void kernel_launch(void* const* d_in, const int* in_sizes, int n_in,
                              void* d_out, int out_size)
{
    const float* p0  = (const float*)d_in[0];
    const float* p1  = (const float*)d_in[1];
    const float* p2  = (const float*)d_in[2];
    const float* tgt = (const float*)d_in[3];

    stage_kernel<<<NBL * NGT, 128>>>(p0, p1, p2, tgt);
    apply_kernel<<<NBL, 128>>>(p0, p1, p2);
    final_kernel<<<1, 256>>>((float*)d_out);
}

// round 11
// speedup vs baseline: 2.5930x; 1.0010x over previous
#include <cuda_runtime.h>
#include <math.h>

// ---------------- constants ----------------
#define MAXW     24            // max candidate-window side
#define NGT      40
#define EPSF     1e-7f
#define FULLMASK 0xffffffffu
#define NBL      192           // 64 batches * 3 levels
#define MAXENT   400
#define KMAX     5             // ceil(576 / 128)
#define LDEPTH   5             // per-lane candidates <= KMAX

struct Stage {
    int   n_pos;
    int   cells[10];
    float biou, cxg, cyg, twt, tht, fx, fy;
};

__device__ Stage g_stage[NBL * NGT];
__device__ float g_focal[NBL * NGT];
__device__ float g_part[NBL * 4];

__device__ __forceinline__ float sigf(float x)  { return 1.0f / (1.0f + expf(-x)); }

__device__ __forceinline__ float fast_splus(float x) {
    return fmaxf(x, 0.0f) + __logf(1.0f + __expf(-fabsf(x)));
}

__device__ __forceinline__ float focal0(float x) {
    float t   = __expf(-fabsf(x));
    float inv = __fdividef(1.0f, 1.0f + t);
    float prob = (x >= 0.0f) ? inv : t * inv;
    float ce0  = fmaxf(x, 0.0f) + __logf(1.0f + t);
    return 0.75f * prob * prob * ce0;
}

// IoU from already-loaded channel values (precise math; feeds floor/n_pos/z)
__device__ __forceinline__ float iou_vals(float p1, float p2, float p3, float p4,
                                          float gxx, float gyy, float s,
                                          float tx1, float ty1, float tx2, float ty2, float tA)
{
    float pcx = (sigf(p1) + gxx) * s;
    float pcy = (sigf(p2) + gyy) * s;
    float pw  = expf(fminf(fmaxf(p3, -5.0f), 5.0f)) * s;
    float ph  = expf(fminf(fmaxf(p4, -5.0f), 5.0f)) * s;
    float px1 = pcx - pw * 0.5f, py1 = pcy - ph * 0.5f;
    float px2 = pcx + pw * 0.5f, py2 = pcy + ph * 0.5f;
    float iw = fmaxf(fminf(px2, tx2) - fmaxf(px1, tx1), 0.0f);
    float ih = fmaxf(fminf(py2, ty2) - fmaxf(py1, ty1), 0.0f);
    float inter = iw * ih;
    float aa = (px2 - px1) * (py2 - py1);
    return inter / (aa + tA - inter + EPSF);
}

__device__ __forceinline__ float pred_iou(const float* __restrict__ pred, int HW, int cell,
                                          float gxx, float gyy, float s,
                                          float tx1, float ty1, float tx2, float ty2, float tA)
{
    return iou_vals(pred[HW + cell], pred[2 * HW + cell], pred[3 * HW + cell], pred[4 * HW + cell],
                    gxx, gyy, s, tx1, ty1, tx2, ty2, tA);
}

// ---------------- Kernel 1: one block per (b,level,gt) ----------------
__global__ void __launch_bounds__(128)
stage_kernel(const float* __restrict__ p0,
             const float* __restrict__ p1,
             const float* __restrict__ p2,
             const float* __restrict__ tgt)
{
    __shared__ float mcC[4][10];   // per-warp extracted top-10 (cost)
    __shared__ int   mcS[4][10];   // per-warp extracted top-10 (slot)
    __shared__ float rls[4];
    __shared__ int   rlc[4];
    __shared__ float red[128];

    const int tid  = threadIdx.x;
    const int lane = tid & 31;
    const int wid  = tid >> 5;

    const int gw    = blockIdx.x;
    const int bl    = gw / NGT;
    const int g     = gw - bl * NGT;
    const int b     = bl / 3;
    const int level = bl % 3;

    const float* predB = (level == 0) ? p0 : (level == 1) ? p1 : p2;
    const int W  = (level == 0) ? 160 : (level == 1) ? 80 : 40;
    const int HW = W * W;
    const float s = (level == 0) ? 0.00625f : (level == 1) ? 0.0125f : 0.025f;
    const float* pred = predB + (long long)b * 7 * HW;

    Stage& st = g_stage[gw];

    // ---- fused dense z=0 focal slice ----
    float fsum = 0.0f;
    {
        const int nv4 = HW / (4 * NGT);
        const float4* v4 = (const float4*)pred + g * nv4;
        for (int i = tid; i < nv4; i += 128) {
            float4 xv = v4[i];
            fsum += focal0(xv.x) + focal0(xv.y) + focal0(xv.z) + focal0(xv.w);
        }
    }

    // ---- target ----
    const float* t = &tgt[b * NGT * 7 + g * 7];
    float cls = t[0], cx = t[1], cy = t[2], w = t[3], h = t[4], fx = t[5], fy = t[6];
    float size = fmaxf(w, h) * 1280.0f;
    bool valid = (cls == 0.0f) &&
                 ((level == 0) ? (size < 128.0f)
                  : (level == 1) ? (size >= 48.0f && size < 288.0f)
                                 : (size >= 128.0f));

    const float INF = __int_as_float(0x7f800000);

    if (valid) {
        float cxg = cx / s, cyg = cy / s;
        float x1b = (cx - w * 0.5f) / s, x2b = (cx + w * 0.5f) / s;
        float y1b = (cy - h * 0.5f) / s, y2b = (cy + h * 0.5f) / s;
        float tx1 = cx - w * 0.5f, ty1 = cy - h * 0.5f;
        float tx2 = cx + w * 0.5f, ty2 = cy + h * 0.5f;
        float tA  = (tx2 - tx1) * (ty2 - ty1);

        int gx0 = max(0, (int)floorf(fminf(cxg - 2.5f, x1b)));
        int gx1 = min(W - 1, (int)ceilf(fmaxf(cxg + 2.5f, x2b)));
        int gy0 = max(0, (int)floorf(fminf(cyg - 2.5f, y1b)));
        int gy1 = min(W - 1, (int)ceilf(fmaxf(cyg + 2.5f, y2b)));
        int wx = gx1 - gx0 + 1, wy = gy1 - gy0 + 1;
        if (wx > MAXW) wx = MAXW;
        if (wy > MAXW) wy = MAXW;
        int nwin = (wx > 0 && wy > 0) ? wx * wy : 0;
        float rwx = 1.0f / (float)wx;   // exact enough: distance to int boundary >= 0.02

        // ---- pass 1: issue ALL window loads; stash grid coords (no div in pass 2) ----
        float v0[KMAX], v1[KMAX], v2[KMAX], v3[KMAX], v4c[KMAX];
        float gX[KMAX], gY[KMAX];
        bool  act[KMAX];
        #pragma unroll
        for (int k = 0; k < KMAX; k++) {
            int si = tid + k * 128;
            act[k] = false;
            if (si < nwin) {
                int iy = (int)(((float)si + 0.5f) * rwx);
                int ix = si - iy * wx;
                float gxx = (float)(gx0 + ix), gyy = (float)(gy0 + iy);
                bool ic = (fabsf(gxx - cxg) < 2.5f) && (fabsf(gyy - cyg) < 2.5f);
                bool ib = (gxx >= x1b) && (gxx < x2b) && (gyy >= y1b) && (gyy < y2b);
                if (ic || ib) {
                    act[k] = true;
                    gX[k] = gxx; gY[k] = gyy;
                    int cell = (gy0 + iy) * W + (gx0 + ix);
                    v0[k] = pred[cell];
                    v1[k] = pred[HW + cell];
                    v2[k] = pred[2 * HW + cell];
                    v3[k] = pred[3 * HW + cell];
                    v4c[k] = pred[4 * HW + cell];
                }
            }
        }

        // ---- pass 2: cost + per-lane sorted top-LDEPTH ----
        float lc[LDEPTH];
        int   ls[LDEPTH];
        #pragma unroll
        for (int i = 0; i < LDEPTH; i++) { lc[i] = INF; ls[i] = 0x7fffffff; }

        float lis = 0.0f;
        int   lnc = 0;
        #pragma unroll
        for (int k = 0; k < KMAX; k++) {
            if (!act[k]) continue;
            int si = tid + k * 128;
            float iou = iou_vals(v1[k], v2[k], v3[k], v4c[k], gX[k], gY[k], s, tx1, ty1, tx2, ty2, tA);
            float c = fast_splus(-v0[k]) - 3.0f * __logf(iou + EPSF);
            lis += iou;
            lnc += 1;
            if (c < lc[LDEPTH - 1]) {
                lc[LDEPTH - 1] = c; ls[LDEPTH - 1] = si;
                #pragma unroll
                for (int i = LDEPTH - 1; i > 0; i--) {
                    if (lc[i] < lc[i - 1]) {
                        float tc = lc[i]; lc[i] = lc[i - 1]; lc[i - 1] = tc;
                        int   ts = ls[i]; ls[i] = ls[i - 1]; ls[i - 1] = ts;
                    }
                }
            }
        }

        // reduce lis/lnc; pre-clear merge buffer
        for (int off = 16; off; off >>= 1) {
            lis += __shfl_xor_sync(FULLMASK, lis, off);
            lnc += __shfl_xor_sync(FULLMASK, lnc, off);
        }
        if (lane == 0) { rls[wid] = lis; rlc[wid] = lnc; }
        if (tid < 40) { mcC[tid / 10][tid % 10] = INF; mcS[tid / 10][tid % 10] = 0x7fffffff; }
        __syncthreads();
        lis = rls[0] + rls[1] + rls[2] + rls[3];
        lnc = rlc[0] + rlc[1] + rlc[2] + rlc[3];

        if (lnc == 0) {
            // fallback (practically unreachable): nearest cell, warp 0 only
            if (wid == 0) {
                float bd = INF; int bc = 0x7fffffff;
                for (int cell = lane; cell < HW; cell += 32) {
                    float gxx = (float)(cell % W), gyy = (float)(cell / W);
                    float d = (gxx - cxg) * (gxx - cxg) + (gyy - cyg) * (gyy - cyg);
                    if (d < bd) { bd = d; bc = cell; }
                }
                for (int off = 16; off; off >>= 1) {
                    float od = __shfl_xor_sync(FULLMASK, bd, off);
                    int   oc = __shfl_xor_sync(FULLMASK, bc, off);
                    if (od < bd || (od == bd && oc < bc)) { bd = od; bc = oc; }
                }
                if (lane == 0) {
                    float gxx = (float)(bc % W), gyy = (float)(bc / W);
                    st.cells[0] = bc;
                    st.n_pos = 1;
                    st.biou  = pred_iou(pred, HW, bc, gxx, gyy, s, tx1, ty1, tx2, ty2, tA);
                    st.cxg = cxg; st.cyg = cyg;
                    st.twt = logf(w / s + EPSF);
                    st.tht = logf(h / s + EPSF);
                    st.fx = fx; st.fy = fy;
                }
            }
        } else {
            const int n_pos = min(min(10, lnc), max(1, (int)floorf(lis)));

            // per-warp extraction: n_pos rounds of shfl-only lexmin + pop
            for (int k = 0; k < n_pos; k++) {
                float hc = lc[0]; int hs = ls[0];
                for (int off = 16; off; off >>= 1) {
                    float oc = __shfl_xor_sync(FULLMASK, hc, off);
                    int   os = __shfl_xor_sync(FULLMASK, hs, off);
                    if (oc < hc || (oc == hc && os < hs)) { hc = oc; hs = os; }
                }
                if (lane == 0) { mcC[wid][k] = hc; mcS[wid][k] = hs; }
                if (lc[0] == hc && ls[0] == hs) {
                    #pragma unroll
                    for (int i = 0; i < LDEPTH - 1; i++) { lc[i] = lc[i + 1]; ls[i] = ls[i + 1]; }
                    lc[LDEPTH - 1] = INF; ls[LDEPTH - 1] = 0x7fffffff;
                }
            }
            __syncthreads();

            // warp 0 merges the 4 sorted lists: n_pos rounds over <=40 candidates
            if (wid == 0) {
                // lane holds candidates j=lane and j=lane+32 (row-major [4][10])
                float ca = mcC[lane >> 3 & 3][0]; // placeholder init below
                // load both candidates explicitly
                float c1 = mcC[lane / 10 < 4 ? lane / 10 : 3][0];
                // -- simpler, direct indexing:
                int j1 = lane;            // 0..31
                int j2 = lane + 32;       // 32..39 valid for lane<8
                float k1 = mcC[j1 / 10][j1 % 10];
                int   s1 = mcS[j1 / 10][j1 % 10];
                float k2 = (lane < 8) ? mcC[j2 / 10][j2 % 10] : INF;
                int   s2v = (lane < 8) ? mcS[j2 / 10][j2 % 10] : 0x7fffffff;
                (void)ca; (void)c1;

                int cell0 = 0;
                for (int k = 0; k < n_pos; k++) {
                    // lane-local min of its two
                    float mc2; int ms2; bool firstIsMin;
                    if (k1 < k2 || (k1 == k2 && s1 < s2v)) { mc2 = k1; ms2 = s1; firstIsMin = true; }
                    else                                    { mc2 = k2; ms2 = s2v; firstIsMin = false; }
                    float hc = mc2; int hs = ms2;
                    for (int off = 16; off; off >>= 1) {
                        float oc = __shfl_xor_sync(FULLMASK, hc, off);
                        int   os = __shfl_xor_sync(FULLMASK, hs, off);
                        if (oc < hc || (oc == hc && os < hs)) { hc = oc; hs = os; }
                    }
                    // decode slot -> cell
                    int iy = hs / wx, ix = hs - iy * wx;
                    int cell = (gy0 + iy) * W + (gx0 + ix);
                    if (k == 0) cell0 = cell;
                    if (lane == 0) st.cells[k] = cell;
                    // pop (slots unique -> one lane owns)
                    if (firstIsMin) { if (k1 == hc && s1 == hs) { k1 = INF; s1 = 0x7fffffff; } }
                    else            { if (k2 == hc && s2v == hs) { k2 = INF; s2v = 0x7fffffff; } }
                }
                if (lane == 0) {
                    float gxx = (float)(cell0 % W), gyy = (float)(cell0 / W);
                    st.n_pos = n_pos;
                    st.biou  = pred_iou(pred, HW, cell0, gxx, gyy, s, tx1, ty1, tx2, ty2, tA);
                    st.cxg = cxg; st.cyg = cyg;
                    st.twt = logf(w / s + EPSF);
                    st.tht = logf(h / s + EPSF);
                    st.fx = fx; st.fy = fy;
                }
            }
        }
    } else {
        if (tid == 0) st.n_pos = 0;
    }
    __syncthreads();

    // ---- focal block reduce ----
    red[tid] = fsum; __syncthreads();
    for (int off = 64; off; off >>= 1) { if (tid < off) red[tid] += red[tid + off]; __syncthreads(); }
    if (tid == 0) g_focal[gw] = red[0];
}

// ---------------- Kernel 2: deterministic parallel apply + sparse losses ----------------
__global__ void __launch_bounds__(128)
apply_kernel(const float* __restrict__ p0,
             const float* __restrict__ p1,
             const float* __restrict__ p2)
{
    __shared__ int   entCell[MAXENT];
    __shared__ int   entG[MAXENT];
    __shared__ float sBiou[NGT], sCxg[NGT], sCyg[NGT], sTwt[NGT], sTht[NGT], sFx[NGT], sFy[NGT];
    __shared__ int   sNp[NGT], sOff[NGT];
    __shared__ int   sM;
    __shared__ float red[128];

    const int bl    = blockIdx.x;
    const int b     = bl / 3;
    const int level = bl % 3;
    const float* pred = (level == 0) ? p0 : (level == 1) ? p1 : p2;
    const int W  = (level == 0) ? 160 : (level == 1) ? 80 : 40;
    const int HW = W * W;
    const float s = (level == 0) ? 0.00625f : (level == 1) ? 0.0125f : 0.025f;
    pred += (long long)b * 7 * HW;

    const int tid = threadIdx.x;

    if (tid < NGT) {
        const Stage& st = g_stage[bl * NGT + tid];
        int np = st.n_pos;
        sNp[tid]   = np;
        sBiou[tid] = st.biou;
        sCxg[tid]  = st.cxg;  sCyg[tid] = st.cyg;
        sTwt[tid]  = st.twt;  sTht[tid] = st.tht;
        sFx[tid]   = st.fx;   sFy[tid]  = st.fy;
    }
    __syncthreads();
    if (tid < NGT) {
        int off = 0;
        #pragma unroll
        for (int g2 = 0; g2 < NGT; g2++) { if (g2 < tid) off += sNp[g2]; }
        sOff[tid] = off;
        if (tid == NGT - 1) sM = off + sNp[tid];
    }
    __syncthreads();
    if (tid < NGT) {
        const Stage& st = g_stage[bl * NGT + tid];
        int off = sOff[tid];
        int np  = sNp[tid];
        for (int k = 0; k < np; k++) { entCell[off + k] = st.cells[k]; entG[off + k] = tid; }
    }
    __syncthreads();
    const int M = sM;

    float corr = (tid < NGT) ? g_focal[bl * NGT + tid] : 0.0f;
    float boxs = 0.0f, foots = 0.0f;
    int   nown = 0;

    for (int e = tid; e < M; e += 128) {
        int c  = entCell[e];
        int ge = entG[e];
        float z = sBiou[ge];
        bool owner = true;
        for (int e2 = 0; e2 < M; e2++) {
            if (entCell[e2] == c && e2 != e) {
                int g2 = entG[e2];
                z = fmaxf(z, sBiou[g2]);
                if (g2 > ge) owner = false;
            }
        }
        if (!owner) continue;
        nown++;

        float gxx = (float)(c % W), gyy = (float)(c / W);

        float x = pred[c];
        float prob = sigf(x);
        float l1e  = log1pf(expf(-fabsf(x)));
        float ce   = fmaxf(x, 0.0f) - x * z + l1e;
        float ce0  = fmaxf(x, 0.0f) + l1e;
        float pt   = prob * z + (1.0f - prob) * (1.0f - z);
        float at   = 0.25f * z + 0.75f * (1.0f - z);
        float om   = 1.0f - pt;
        corr += at * om * om * ce - 0.75f * prob * prob * ce0;

        float p1v = pred[HW + c], p2v = pred[2 * HW + c];
        float p3v = pred[3 * HW + c], p4v = pred[4 * HW + c];
        float pcx = (sigf(p1v) + gxx) * s;
        float pcy = (sigf(p2v) + gyy) * s;
        float pw  = expf(fminf(fmaxf(p3v, -5.0f), 5.0f)) * s;
        float ph  = expf(fminf(fmaxf(p4v, -5.0f), 5.0f)) * s;
        float tcx = sCxg[ge] * s;
        float tcy = sCyg[ge] * s;
        float tw  = expf(sTwt[ge]) * s;
        float th  = expf(sTht[ge]) * s;
        float px1 = pcx - pw * 0.5f, py1 = pcy - ph * 0.5f;
        float px2 = pcx + pw * 0.5f, py2 = pcy + ph * 0.5f;
        float qx1 = tcx - tw * 0.5f, qy1 = tcy - th * 0.5f;
        float qx2 = tcx + tw * 0.5f, qy2 = tcy + th * 0.5f;
        float iw = fmaxf(fminf(px2, qx2) - fmaxf(px1, qx1), 0.0f);
        float ih = fmaxf(fminf(py2, qy2) - fmaxf(py1, qy1), 0.0f);
        float inter = iw * ih;
        float uni = pw * ph + tw * th - inter + EPSF;
        float iou = inter / uni;
        float rho2 = (pcx - tcx) * (pcx - tcx) + (pcy - tcy) * (pcy - tcy);
        float cw  = fmaxf(px2, qx2) - fminf(px1, qx1);
        float chh = fmaxf(py2, qy2) - fminf(py1, qy1);
        float c2  = cw * cw + chh * chh + EPSF;
        float dat = atanf(tw / (th + EPSF)) - atanf(pw / (ph + EPSF));
        float v = 0.4052847345693511f * dat * dat;
        float alpha = v / (1.0f - iou + v + EPSF);
        float ciou = iou - rho2 / c2 - alpha * v;
        boxs += 1.0f - ciou;

        float p5v = pred[5 * HW + c], p6v = pred[6 * HW + c];
        float d1 = fabsf(sigf(p5v) - sFx[ge]);
        float d2 = fabsf(sigf(p6v) - sFy[ge]);
        float s1 = (d1 < 1.0f) ? 0.5f * d1 * d1 : d1 - 0.5f;
        float s2 = (d2 < 1.0f) ? 0.5f * d2 * d2 : d2 - 0.5f;
        foots += s1 + s2;
    }

    red[tid] = corr; __syncthreads();
    for (int off = 64; off; off >>= 1) { if (tid < off) red[tid] += red[tid + off]; __syncthreads(); }
    if (tid == 0) g_part[bl * 4 + 0] = red[0];
    __syncthreads();
    red[tid] = boxs; __syncthreads();
    for (int off = 64; off; off >>= 1) { if (tid < off) red[tid] += red[tid + off]; __syncthreads(); }
    if (tid == 0) g_part[bl * 4 + 1] = red[0];
    __syncthreads();
    red[tid] = foots; __syncthreads();
    for (int off = 64; off; off >>= 1) { if (tid < off) red[tid] += red[tid + off]; __syncthreads(); }
    if (tid == 0) g_part[bl * 4 + 2] = red[0];
    __syncthreads();
    red[tid] = (float)nown; __syncthreads();
    for (int off = 64; off; off >>= 1) { if (tid < off) red[tid] += red[tid + off]; __syncthreads(); }
    if (tid == 0) g_part[bl * 4 + 3] = red[0];
}

// ---------------- Kernel 3: deterministic final combine ----------------
__global__ void __launch_bounds__(256)
final_kernel(float* __restrict__ out)
{
    __shared__ float red[256];
    int t = threadIdx.x;
    float v = 0.0f;
    if (t < NBL) {
        int l = t % 3;
        float HWf = (l == 0) ? 25600.0f : (l == 1) ? 6400.0f : 1600.0f;
        float objt  = g_part[t * 4 + 0];
        float boxs  = g_part[t * 4 + 1];
        float foots = g_part[t * 4 + 2];
        float npos  = fmaxf(g_part[t * 4 + 3], 1.0f);
        v = objt / HWf + 5.0f * boxs / npos + foots / npos;
    }
    red[t] = v; __syncthreads();
    for (int o = 128; o; o >>= 1) { if (t < o) red[t] += red[t + o]; __syncthreads(); }
    if (t == 0) out[0] = red[0] / 64.0f;
}

// ---------------- launch ----------------
extern "C" void kernel_launch(void* const* d_in, const int* in_sizes, int n_in,
                              void* d_out, int out_size)
{
    const float* p0  = (const float*)d_in[0];
    const float* p1  = (const float*)d_in[1];
    const float* p2  = (const float*)d_in[2];
    const float* tgt = (const float*)d_in[3];

    stage_kernel<<<NBL * NGT, 128>>>(p0, p1, p2, tgt);
    apply_kernel<<<NBL, 128>>>(p0, p1, p2);
    final_kernel<<<1, 256>>>((float*)d_out);
}

// round 13
// speedup vs baseline: 2.9357x; 1.1322x over previous
#include <cuda_runtime.h>
#include <math.h>

// ---------------- constants ----------------
#define MAXW     24            // max candidate-window side
#define NGT      40
#define EPSF     1e-7f
#define FULLMASK 0xffffffffu
#define NBL      192           // 64 batches * 3 levels
#define MAXENT   400
#define KMAX     5             // ceil(576 / 128)
#define LDEPTH   5             // per-lane candidates <= KMAX
#define NFB      11            // focal chunks per batch: 8 (lvl0) + 2 (lvl1) + 1 (lvl2)
#define NFOCAL   (64 * NFB)    // 704 focal blocks
#define NSTAGE   (NBL * NGT)   // 7680 stage blocks

struct Stage {
    int   n_pos;
    int   cells[10];
    float biou, cxg, cyg, twt, tht, fx, fy;
};

__device__ Stage g_stage[NSTAGE];
__device__ float g_fpart[NFOCAL];   // dense z=0 focal partials
__device__ float g_part[NBL * 4];   // per (b,level): obj_corr, box_sum, foot_sum, npos
__device__ int   g_cnt = 0;         // apply-completion counter (self-resetting)

__device__ __forceinline__ float sigf(float x)  { return 1.0f / (1.0f + expf(-x)); }

__device__ __forceinline__ float fast_splus(float x) {
    return fmaxf(x, 0.0f) + __logf(1.0f + __expf(-fabsf(x)));
}

// fast z=0 focal term: 0.75 * sigmoid(x)^2 * softplus(x)
__device__ __forceinline__ float focal0(float x) {
    float t   = __expf(-fabsf(x));
    float inv = __fdividef(1.0f, 1.0f + t);
    float prob = (x >= 0.0f) ? inv : t * inv;
    float ce0  = fmaxf(x, 0.0f) + __logf(1.0f + t);
    return 0.75f * prob * prob * ce0;
}

// IoU from already-loaded channel values (precise math; feeds floor/n_pos/z)
__device__ __forceinline__ float iou_vals(float p1, float p2, float p3, float p4,
                                          float gxx, float gyy, float s,
                                          float tx1, float ty1, float tx2, float ty2, float tA)
{
    float pcx = (sigf(p1) + gxx) * s;
    float pcy = (sigf(p2) + gyy) * s;
    float pw  = expf(fminf(fmaxf(p3, -5.0f), 5.0f)) * s;
    float ph  = expf(fminf(fmaxf(p4, -5.0f), 5.0f)) * s;
    float px1 = pcx - pw * 0.5f, py1 = pcy - ph * 0.5f;
    float px2 = pcx + pw * 0.5f, py2 = pcy + ph * 0.5f;
    float iw = fmaxf(fminf(px2, tx2) - fmaxf(px1, tx1), 0.0f);
    float ih = fmaxf(fminf(py2, ty2) - fmaxf(py1, ty1), 0.0f);
    float inter = iw * ih;
    float aa = (px2 - px1) * (py2 - py1);
    return inter / (aa + tA - inter + EPSF);
}

__device__ __forceinline__ float pred_iou(const float* __restrict__ pred, int HW, int cell,
                                          float gxx, float gyy, float s,
                                          float tx1, float ty1, float tx2, float ty2, float tA)
{
    return iou_vals(pred[HW + cell], pred[2 * HW + cell], pred[3 * HW + cell], pred[4 * HW + cell],
                    gxx, gyy, s, tx1, ty1, tx2, ty2, tA);
}

// ---------------- Kernel 1: stage blocks (per GT) + focal blocks, one grid ----------------
__global__ void __launch_bounds__(128)
stage_kernel(const float* __restrict__ p0,
             const float* __restrict__ p1,
             const float* __restrict__ p2,
             const float* __restrict__ tgt)
{
    const int tid  = threadIdx.x;
    const int lane = tid & 31;
    const int wid  = tid >> 5;

    // ================= focal blocks =================
    if (blockIdx.x >= NSTAGE) {
        __shared__ float fsm[4];
        const int fid = blockIdx.x - NSTAGE;
        const int b   = fid / NFB;
        const int j   = fid - b * NFB;
        const float* base;
        int off, cnt;
        if (j < 8)       { base = p0 + (long long)b * 7 * 25600; off = j * 3200;       cnt = 3200; }
        else if (j < 10) { base = p1 + (long long)b * 7 * 6400;  off = (j - 8) * 3200; cnt = 3200; }
        else             { base = p2 + (long long)b * 7 * 1600;  off = 0;              cnt = 1600; }

        const float4* v4 = (const float4*)(base + off);
        float sum = 0.0f;
        for (int i = tid; i < cnt / 4; i += 128) {
            float4 xv = v4[i];
            sum += focal0(xv.x) + focal0(xv.y) + focal0(xv.z) + focal0(xv.w);
        }
        for (int o = 16; o; o >>= 1) sum += __shfl_xor_sync(FULLMASK, sum, o);
        if (lane == 0) fsm[wid] = sum;
        __syncthreads();
        if (tid == 0) g_fpart[fid] = fsm[0] + fsm[1] + fsm[2] + fsm[3];
        return;
    }

    // ================= stage blocks =================
    __shared__ float mcC[4][10];
    __shared__ int   mcS[4][10];
    __shared__ float rls[4];
    __shared__ int   rlc[4];

    const int gw    = blockIdx.x;
    const int bl    = gw / NGT;
    const int g     = gw - bl * NGT;
    const int b     = bl / 3;
    const int level = bl % 3;

    Stage& st = g_stage[gw];

    const float* t = &tgt[b * NGT * 7 + g * 7];
    float cls = t[0], cx = t[1], cy = t[2], w = t[3], h = t[4], fx = t[5], fy = t[6];
    float size = fmaxf(w, h) * 1280.0f;
    bool valid = (cls == 0.0f) &&
                 ((level == 0) ? (size < 128.0f)
                  : (level == 1) ? (size >= 48.0f && size < 288.0f)
                                 : (size >= 128.0f));
    if (!valid) {
        if (tid == 0) st.n_pos = 0;
        return;
    }

    const float* predB = (level == 0) ? p0 : (level == 1) ? p1 : p2;
    const int W  = (level == 0) ? 160 : (level == 1) ? 80 : 40;
    const int HW = W * W;
    const float s = (level == 0) ? 0.00625f : (level == 1) ? 0.0125f : 0.025f;
    const float* pred = predB + (long long)b * 7 * HW;

    const float INF = __int_as_float(0x7f800000);

    float cxg = cx / s, cyg = cy / s;
    float x1b = (cx - w * 0.5f) / s, x2b = (cx + w * 0.5f) / s;
    float y1b = (cy - h * 0.5f) / s, y2b = (cy + h * 0.5f) / s;
    float tx1 = cx - w * 0.5f, ty1 = cy - h * 0.5f;
    float tx2 = cx + w * 0.5f, ty2 = cy + h * 0.5f;
    float tA  = (tx2 - tx1) * (ty2 - ty1);

    int gx0 = max(0, (int)floorf(fminf(cxg - 2.5f, x1b)));
    int gx1 = min(W - 1, (int)ceilf(fmaxf(cxg + 2.5f, x2b)));
    int gy0 = max(0, (int)floorf(fminf(cyg - 2.5f, y1b)));
    int gy1 = min(W - 1, (int)ceilf(fmaxf(cyg + 2.5f, y2b)));
    int wx = gx1 - gx0 + 1, wy = gy1 - gy0 + 1;
    if (wx > MAXW) wx = MAXW;
    if (wy > MAXW) wy = MAXW;
    int nwin = (wx > 0 && wy > 0) ? wx * wy : 0;
    float rwx = 1.0f / (float)wx;   // exact: si<576, wx<=24, boundary margin >= 0.02

    // ---- pass 1: issue ALL window loads; stash grid coords ----
    float v0[KMAX], v1[KMAX], v2[KMAX], v3[KMAX], v4c[KMAX];
    float gX[KMAX], gY[KMAX];
    bool  act[KMAX];
    #pragma unroll
    for (int k = 0; k < KMAX; k++) {
        int si = tid + k * 128;
        act[k] = false;
        if (si < nwin) {
            int iy = (int)(((float)si + 0.5f) * rwx);
            int ix = si - iy * wx;
            float gxx = (float)(gx0 + ix), gyy = (float)(gy0 + iy);
            bool ic = (fabsf(gxx - cxg) < 2.5f) && (fabsf(gyy - cyg) < 2.5f);
            bool ib = (gxx >= x1b) && (gxx < x2b) && (gyy >= y1b) && (gyy < y2b);
            if (ic || ib) {
                act[k] = true;
                gX[k] = gxx; gY[k] = gyy;
                int cell = (gy0 + iy) * W + (gx0 + ix);
                v0[k] = pred[cell];
                v1[k] = pred[HW + cell];
                v2[k] = pred[2 * HW + cell];
                v3[k] = pred[3 * HW + cell];
                v4c[k] = pred[4 * HW + cell];
            }
        }
    }

    // ---- pass 2: cost + per-lane sorted top-LDEPTH ----
    float lc[LDEPTH];
    int   ls[LDEPTH];
    #pragma unroll
    for (int i = 0; i < LDEPTH; i++) { lc[i] = INF; ls[i] = 0x7fffffff; }

    float lis = 0.0f;
    int   lnc = 0;
    #pragma unroll
    for (int k = 0; k < KMAX; k++) {
        if (!act[k]) continue;
        int si = tid + k * 128;
        float iou = iou_vals(v1[k], v2[k], v3[k], v4c[k], gX[k], gY[k], s, tx1, ty1, tx2, ty2, tA);
        float c = fast_splus(-v0[k]) - 3.0f * __logf(iou + EPSF);
        lis += iou;
        lnc += 1;
        if (c < lc[LDEPTH - 1]) {
            lc[LDEPTH - 1] = c; ls[LDEPTH - 1] = si;
            #pragma unroll
            for (int i = LDEPTH - 1; i > 0; i--) {
                if (lc[i] < lc[i - 1]) {
                    float tc = lc[i]; lc[i] = lc[i - 1]; lc[i - 1] = tc;
                    int   ts = ls[i]; ls[i] = ls[i - 1]; ls[i - 1] = ts;
                }
            }
        }
    }

    // reduce lis/lnc; pre-clear merge buffer
    for (int off = 16; off; off >>= 1) {
        lis += __shfl_xor_sync(FULLMASK, lis, off);
        lnc += __shfl_xor_sync(FULLMASK, lnc, off);
    }
    if (lane == 0) { rls[wid] = lis; rlc[wid] = lnc; }
    if (tid < 40) { mcC[tid / 10][tid % 10] = INF; mcS[tid / 10][tid % 10] = 0x7fffffff; }
    __syncthreads();
    lis = rls[0] + rls[1] + rls[2] + rls[3];
    lnc = rlc[0] + rlc[1] + rlc[2] + rlc[3];

    if (lnc == 0) {
        // fallback (practically unreachable): nearest cell, warp 0 only
        if (wid == 0) {
            float bd = INF; int bc = 0x7fffffff;
            for (int cell = lane; cell < HW; cell += 32) {
                float gxx = (float)(cell % W), gyy = (float)(cell / W);
                float d = (gxx - cxg) * (gxx - cxg) + (gyy - cyg) * (gyy - cyg);
                if (d < bd) { bd = d; bc = cell; }
            }
            for (int off = 16; off; off >>= 1) {
                float od = __shfl_xor_sync(FULLMASK, bd, off);
                int   oc = __shfl_xor_sync(FULLMASK, bc, off);
                if (od < bd || (od == bd && oc < bc)) { bd = od; bc = oc; }
            }
            if (lane == 0) {
                float gxx = (float)(bc % W), gyy = (float)(bc / W);
                st.cells[0] = bc;
                st.n_pos = 1;
                st.biou  = pred_iou(pred, HW, bc, gxx, gyy, s, tx1, ty1, tx2, ty2, tA);
                st.cxg = cxg; st.cyg = cyg;
                st.twt = logf(w / s + EPSF);
                st.tht = logf(h / s + EPSF);
                st.fx = fx; st.fy = fy;
            }
        }
        return;
    }

    const int n_pos = min(min(10, lnc), max(1, (int)floorf(lis)));

    // per-warp extraction: n_pos rounds of shfl-only lexmin + pop
    for (int k = 0; k < n_pos; k++) {
        float hc = lc[0]; int hs = ls[0];
        for (int off = 16; off; off >>= 1) {
            float oc = __shfl_xor_sync(FULLMASK, hc, off);
            int   os = __shfl_xor_sync(FULLMASK, hs, off);
            if (oc < hc || (oc == hc && os < hs)) { hc = oc; hs = os; }
        }
        if (lane == 0) { mcC[wid][k] = hc; mcS[wid][k] = hs; }
        if (lc[0] == hc && ls[0] == hs) {
            #pragma unroll
            for (int i = 0; i < LDEPTH - 1; i++) { lc[i] = lc[i + 1]; ls[i] = ls[i + 1]; }
            lc[LDEPTH - 1] = INF; ls[LDEPTH - 1] = 0x7fffffff;
        }
    }
    __syncthreads();

    // warp 0 merges the 4 sorted lists: n_pos rounds over <=40 candidates
    if (wid == 0) {
        int j1 = lane;            // 0..31
        int j2 = lane + 32;       // 32..39 valid for lane<8
        float k1 = mcC[j1 / 10][j1 % 10];
        int   s1 = mcS[j1 / 10][j1 % 10];
        float k2 = (lane < 8) ? mcC[j2 / 10][j2 % 10] : INF;
        int   s2v = (lane < 8) ? mcS[j2 / 10][j2 % 10] : 0x7fffffff;

        int cell0 = 0;
        for (int k = 0; k < n_pos; k++) {
            float mc2; int ms2; bool firstIsMin;
            if (k1 < k2 || (k1 == k2 && s1 < s2v)) { mc2 = k1; ms2 = s1; firstIsMin = true; }
            else                                    { mc2 = k2; ms2 = s2v; firstIsMin = false; }
            float hc = mc2; int hs = ms2;
            for (int off = 16; off; off >>= 1) {
                float oc = __shfl_xor_sync(FULLMASK, hc, off);
                int   os = __shfl_xor_sync(FULLMASK, hs, off);
                if (oc < hc || (oc == hc && os < hs)) { hc = oc; hs = os; }
            }
            int iy = hs / wx, ix = hs - iy * wx;
            int cell = (gy0 + iy) * W + (gx0 + ix);
            if (k == 0) cell0 = cell;
            if (lane == 0) st.cells[k] = cell;
            if (firstIsMin) { if (k1 == hc && s1 == hs) { k1 = INF; s1 = 0x7fffffff; } }
            else            { if (k2 == hc && s2v == hs) { k2 = INF; s2v = 0x7fffffff; } }
        }
        if (lane == 0) {
            float gxx = (float)(cell0 % W), gyy = (float)(cell0 / W);
            st.n_pos = n_pos;
            st.biou  = pred_iou(pred, HW, cell0, gxx, gyy, s, tx1, ty1, tx2, ty2, tA);
            st.cxg = cxg; st.cyg = cyg;
            st.twt = logf(w / s + EPSF);
            st.tht = logf(h / s + EPSF);
            st.fx = fx; st.fy = fy;
        }
    }
}

// ---------------- Kernel 2: apply + fused final combine ----------------
__global__ void __launch_bounds__(128)
apply_kernel(const float* __restrict__ p0,
             const float* __restrict__ p1,
             const float* __restrict__ p2,
             float* __restrict__ out)
{
    __shared__ int   entCell[MAXENT];
    __shared__ int   entG[MAXENT];
    __shared__ float sBiou[NGT], sCxg[NGT], sCyg[NGT], sTwt[NGT], sTht[NGT], sFx[NGT], sFy[NGT];
    __shared__ int   sNp[NGT], sOff[NGT];
    __shared__ int   sM;
    __shared__ float red[128];
    __shared__ int   sLast;

    const int bl    = blockIdx.x;
    const int b     = bl / 3;
    const int level = bl % 3;
    const float* pred = (level == 0) ? p0 : (level == 1) ? p1 : p2;
    const int W  = (level == 0) ? 160 : (level == 1) ? 80 : 40;
    const int HW = W * W;
    const float s = (level == 0) ? 0.00625f : (level == 1) ? 0.0125f : 0.025f;
    pred += (long long)b * 7 * HW;

    const int tid = threadIdx.x;

    if (tid < NGT) {
        const Stage& st = g_stage[bl * NGT + tid];
        int np = st.n_pos;
        sNp[tid]   = np;
        sBiou[tid] = st.biou;
        sCxg[tid]  = st.cxg;  sCyg[tid] = st.cyg;
        sTwt[tid]  = st.twt;  sTht[tid] = st.tht;
        sFx[tid]   = st.fx;   sFy[tid]  = st.fy;
    }
    __syncthreads();
    if (tid < NGT) {
        int off = 0;
        #pragma unroll
        for (int g2 = 0; g2 < NGT; g2++) { if (g2 < tid) off += sNp[g2]; }
        sOff[tid] = off;
        if (tid == NGT - 1) sM = off + sNp[tid];
    }
    __syncthreads();
    if (tid < NGT) {
        const Stage& st = g_stage[bl * NGT + tid];
        int off = sOff[tid];
        int np  = sNp[tid];
        for (int k = 0; k < np; k++) { entCell[off + k] = st.cells[k]; entG[off + k] = tid; }
    }
    __syncthreads();
    const int M = sM;

    // fold dense focal partials (fixed mapping, deterministic)
    const int nf = (level == 0) ? 8 : (level == 1) ? 2 : 1;
    const int f0 = (level == 0) ? 0 : (level == 1) ? 8 : 10;
    float corr = (tid < nf) ? g_fpart[b * NFB + f0 + tid] : 0.0f;
    float boxs = 0.0f, foots = 0.0f;
    int   nown = 0;

    for (int e = tid; e < M; e += 128) {
        int c  = entCell[e];
        int ge = entG[e];
        float z = sBiou[ge];
        bool owner = true;
        for (int e2 = 0; e2 < M; e2++) {
            if (entCell[e2] == c && e2 != e) {
                int g2 = entG[e2];
                z = fmaxf(z, sBiou[g2]);
                if (g2 > ge) owner = false;
            }
        }
        if (!owner) continue;
        nown++;

        float gxx = (float)(c % W), gyy = (float)(c / W);

        float x = pred[c];
        float prob = sigf(x);
        float l1e  = log1pf(expf(-fabsf(x)));
        float ce   = fmaxf(x, 0.0f) - x * z + l1e;
        float ce0  = fmaxf(x, 0.0f) + l1e;
        float pt   = prob * z + (1.0f - prob) * (1.0f - z);
        float at   = 0.25f * z + 0.75f * (1.0f - z);
        float om   = 1.0f - pt;
        corr += at * om * om * ce - 0.75f * prob * prob * ce0;

        float p1v = pred[HW + c], p2v = pred[2 * HW + c];
        float p3v = pred[3 * HW + c], p4v = pred[4 * HW + c];
        float pcx = (sigf(p1v) + gxx) * s;
        float pcy = (sigf(p2v) + gyy) * s;
        float pw  = expf(fminf(fmaxf(p3v, -5.0f), 5.0f)) * s;
        float ph  = expf(fminf(fmaxf(p4v, -5.0f), 5.0f)) * s;
        float tcx = sCxg[ge] * s;
        float tcy = sCyg[ge] * s;
        float tw  = expf(sTwt[ge]) * s;
        float th  = expf(sTht[ge]) * s;
        float px1 = pcx - pw * 0.5f, py1 = pcy - ph * 0.5f;
        float px2 = pcx + pw * 0.5f, py2 = pcy + ph * 0.5f;
        float qx1 = tcx - tw * 0.5f, qy1 = tcy - th * 0.5f;
        float qx2 = tcx + tw * 0.5f, qy2 = tcy + th * 0.5f;
        float iw = fmaxf(fminf(px2, qx2) - fmaxf(px1, qx1), 0.0f);
        float ih = fmaxf(fminf(py2, qy2) - fmaxf(py1, qy1), 0.0f);
        float inter = iw * ih;
        float uni = pw * ph + tw * th - inter + EPSF;
        float iou = inter / uni;
        float rho2 = (pcx - tcx) * (pcx - tcx) + (pcy - tcy) * (pcy - tcy);
        float cw  = fmaxf(px2, qx2) - fminf(px1, qx1);
        float chh = fmaxf(py2, qy2) - fminf(py1, qy1);
        float c2  = cw * cw + chh * chh + EPSF;
        float dat = atanf(tw / (th + EPSF)) - atanf(pw / (ph + EPSF));
        float v = 0.4052847345693511f * dat * dat;
        float alpha = v / (1.0f - iou + v + EPSF);
        float ciou = iou - rho2 / c2 - alpha * v;
        boxs += 1.0f - ciou;

        float p5v = pred[5 * HW + c], p6v = pred[6 * HW + c];
        float d1 = fabsf(sigf(p5v) - sFx[ge]);
        float d2 = fabsf(sigf(p6v) - sFy[ge]);
        float s1 = (d1 < 1.0f) ? 0.5f * d1 * d1 : d1 - 0.5f;
        float s2 = (d2 < 1.0f) ? 0.5f * d2 * d2 : d2 - 0.5f;
        foots += s1 + s2;
    }

    red[tid] = corr; __syncthreads();
    for (int off = 64; off; off >>= 1) { if (tid < off) red[tid] += red[tid + off]; __syncthreads(); }
    if (tid == 0) g_part[bl * 4 + 0] = red[0];
    __syncthreads();
    red[tid] = boxs; __syncthreads();
    for (int off = 64; off; off >>= 1) { if (tid < off) red[tid] += red[tid + off]; __syncthreads(); }
    if (tid == 0) g_part[bl * 4 + 1] = red[0];
    __syncthreads();
    red[tid] = foots; __syncthreads();
    for (int off = 64; off; off >>= 1) { if (tid < off) red[tid] += red[tid + off]; __syncthreads(); }
    if (tid == 0) g_part[bl * 4 + 2] = red[0];
    __syncthreads();
    red[tid] = (float)nown; __syncthreads();
    for (int off = 64; off; off >>= 1) { if (tid < off) red[tid] += red[tid + off]; __syncthreads(); }
    if (tid == 0) g_part[bl * 4 + 3] = red[0];
    __syncthreads();

    // ---- fused final combine: last block to finish does it ----
    __threadfence();
    if (tid == 0) {
        int old = atomicAdd(&g_cnt, 1);
        sLast = (old == NBL - 1) ? 1 : 0;
    }
    __syncthreads();
    if (sLast) {
        float v = 0.0f;
        for (int i = tid; i < NBL; i += 128) {
            int l = i % 3;
            float HWf = (l == 0) ? 25600.0f : (l == 1) ? 6400.0f : 1600.0f;
            float objt  = g_part[i * 4 + 0];
            float bxs   = g_part[i * 4 + 1];
            float fts   = g_part[i * 4 + 2];
            float npos  = fmaxf(g_part[i * 4 + 3], 1.0f);
            v += objt / HWf + 5.0f * bxs / npos + fts / npos;
        }
        red[tid] = v; __syncthreads();
        for (int off = 64; off; off >>= 1) { if (tid < off) red[tid] += red[tid + off]; __syncthreads(); }
        if (tid == 0) {
            out[0] = red[0] / 64.0f;
            g_cnt = 0;   // reset for next graph replay
        }
    }
}

// ---------------- launch ----------------
extern "C" void kernel_launch(void* const* d_in, const int* in_sizes, int n_in,
                              void* d_out, int out_size)
{
    const float* p0  = (const float*)d_in[0];
    const float* p1  = (const float*)d_in[1];
    const float* p2  = (const float*)d_in[2];
    const float* tgt = (const float*)d_in[3];

    stage_kernel<<<NSTAGE + NFOCAL, 128>>>(p0, p1, p2, tgt);
    apply_kernel<<<NBL, 128>>>(p0, p1, p2, (float*)d_out);
}